// round 11
// baseline (speedup 1.0000x reference)
#include <cuda_runtime.h>
#include <cuda_fp16.h>

#define SVOL  4096000        // 160^3
#define NTOT  8192000        // 2 * 160^3
#define NQ    2048000        // NTOT / 4

// ---- p skeleton smem layout (halves), tile 32x32, zchunk 16, 2 z-slices per iter ----
#define OFF_STAGE 0          // 2 x [36][48]   (stride 1728)
#define OFF_ROWMN 3456       // 2 x [36][40]   (stride 1440)
#define OFF_M2D   6336       // ring4 [34][40] (stride 1360)
#define OFF_ERO   11776      // ring3 [34][40] (stride 1360)
#define OFF_RMAX  15856      // 2 x [34][32]   (stride 1088)
#define OFF_E2D   18032      // ring4 [32][32] (stride 1024)
#define SM_HALVES 22128
#define SM_BYTES  (SM_HALVES * 2)   // 44256

// ---- y bit skeleton smem layout (words) ----
#define W5    5
#define WSL   800
#define WBAT  128000
#define YW    256000
#define YOFF_X   0           // [800]
#define YOFF_WH  800         // ring3 [800]
#define YOFF_E   3200        // ring2 [800]
#define YOFF_D   4800        // ring3 [800]

#define HPINF __ushort_as_half((unsigned short)0x7C00)
#define HNINF __ushort_as_half((unsigned short)0xFC00)

struct __align__(8) h4 { __half2 a, b; };

__device__ double g_acc[14];
__device__ __half g_Xp[NTOT];
__device__ __half g_Xp2[NTOT];
__device__ __half g_Porig[NTOT];
__device__ unsigned int g_Yb0[YW];
__device__ unsigned int g_Yb[YW];
__device__ unsigned int g_Yb2[YW];

__device__ __forceinline__ h4 h4fill(__half v) {
    h4 o; o.a = __half2half2(v); o.b = o.a; return o;
}
__device__ __forceinline__ h4 h4min3(h4 x, h4 y, h4 z) {
    h4 o;
    o.a = __hmin2(x.a, __hmin2(y.a, z.a));
    o.b = __hmin2(x.b, __hmin2(y.b, z.b));
    return o;
}
__device__ __forceinline__ h4 h4max3(h4 x, h4 y, h4 z) {
    h4 o;
    o.a = __hmax2(x.a, __hmax2(y.a, z.a));
    o.b = __hmax2(x.b, __hmax2(y.b, z.b));
    return o;
}
__device__ __forceinline__ h4 shiftMin(__half l, h4 c, __half r) {
    __half2 sl  = __halves2half2(l, __low2half(c.a));
    __half2 sr  = __halves2half2(__high2half(c.a), __low2half(c.b));
    __half2 sr2 = __halves2half2(__high2half(c.b), r);
    h4 o;
    o.a = __hmin2(__hmin2(sl, c.a), sr);
    o.b = __hmin2(__hmin2(sr, c.b), sr2);
    return o;
}
__device__ __forceinline__ h4 shiftMax(__half l, h4 c, __half r) {
    __half2 sl  = __halves2half2(l, __low2half(c.a));
    __half2 sr  = __halves2half2(__high2half(c.a), __low2half(c.b));
    __half2 sr2 = __halves2half2(__high2half(c.b), r);
    h4 o;
    o.a = __hmax2(__hmax2(sl, c.a), sr);
    o.b = __hmax2(__hmax2(sr, c.b), sr2);
    return o;
}

template <int NV>
__device__ __forceinline__ void blockAddTo(const float* vals, double* gout) {
    __shared__ float red[NV][8];
    int tid = threadIdx.x, lane = tid & 31, w = tid >> 5;
#pragma unroll
    for (int k = 0; k < NV; k++) {
        float v = vals[k];
#pragma unroll
        for (int o = 16; o; o >>= 1) v += __shfl_down_sync(0xffffffffu, v, o);
        if (lane == 0) red[k][w] = v;
    }
    __syncthreads();
    if (w == 0) {
#pragma unroll
        for (int k = 0; k < NV; k++) {
            float v = (lane < 8) ? red[k][lane] : 0.0f;
#pragma unroll
            for (int o = 4; o; o >>= 1) v += __shfl_down_sync(0xffffffffu, v, o);
            if (lane == 0) atomicAdd(&gout[k], (double)v);
        }
    }
}

__global__ void k_zero() {
    if (threadIdx.x < 14) g_acc[threadIdx.x] = 0.0;
}

__global__ void __launch_bounds__(256) k_init(const float* __restrict__ logits,
                                              const int* __restrict__ target) {
    __shared__ unsigned char nib[256];
    int tid = threadIdx.x;
    int q = blockIdx.x * 256 + tid;
    int e = q * 4;
    int b = (e >= SVOL) ? 1 : 0;
    int s = e - b * SVOL;
    const float* lp = logits + (size_t)b * 3 * SVOL + s;
    float4 L0 = *(const float4*)(lp);
    float4 L1 = *(const float4*)(lp + SVOL);
    float4 L2 = *(const float4*)(lp + 2 * SVOL);
    int4 ti = ((const int4*)target)[q];
    int tg[4] = {ti.x, ti.y, ti.z, ti.w};
    float a0[4] = {L0.x, L0.y, L0.z, L0.w};
    float a1[4] = {L1.x, L1.y, L1.z, L1.w};
    float a2[4] = {L2.x, L2.y, L2.z, L2.w};

    float ce = 0.f, i0 = 0.f, i1 = 0.f, i2 = 0.f;
    float s0 = 0.f, s1 = 0.f, s2 = 0.f, c0 = 0.f, c1 = 0.f, c2 = 0.f;
    float pv[4];
    unsigned nb = 0;
#pragma unroll
    for (int j = 0; j < 4; j++) {
        float x0 = a0[j], x1 = a1[j], x2 = a2[j];
        float m = fmaxf(x0, fmaxf(x1, x2));
        float e0 = __expf(x0 - m), e1 = __expf(x1 - m), e2 = __expf(x2 - m);
        float sum = e0 + e1 + e2;
        float inv = 1.0f / sum;
        float p0 = e0 * inv, p1 = e1 * inv, p2 = e2 * inv;
        float ls = __logf(sum);
        int t = tg[j];
        float lt = (t == 0) ? x0 : ((t == 1) ? x1 : x2);
        ce += (m + ls - lt);
        s0 += p0; s1 += p1; s2 += p2;
        if (t == 0)      { i0 += p0; c0 += 1.f; }
        else if (t == 1) { i1 += p1; c1 += 1.f; }
        else             { i2 += p2; c2 += 1.f; }
        pv[j] = fminf(fmaxf(1.0f - p0, 0.0f), 1.0f);
        if (t != 0) nb |= (1u << j);
    }
    h4 PV;
    PV.a = __floats2half2_rn(pv[0], pv[1]);
    PV.b = __floats2half2_rn(pv[2], pv[3]);
    ((h4*)g_Xp)[q] = PV;
    ((h4*)g_Porig)[q] = PV;
    nib[tid] = (unsigned char)nb;
    __syncthreads();
    if (tid < 32) {
        unsigned w = 0;
#pragma unroll
        for (int k = 0; k < 8; k++) w |= ((unsigned)nib[tid * 8 + k]) << (4 * k);
        int wi = blockIdx.x * 32 + tid;
        g_Yb0[wi] = w;
        g_Yb[wi] = w;
    }

    float vals[10] = {ce, i0, i1, i2, s0, s1, s2, c0, c1, c2};
    blockAddTo<10>(vals, g_acc);
}

// ---------------- merged skeleton iteration -----------------
// blocks [0,500): fp16 p skeleton (tile 32x32, zchunk 16, 2 slices/iter).
// blocks [500,580): bit y skeleton (chunk 4).

__device__ __forceinline__ void p_skel_block(__half* sm, int bi, int flip) {
    __half* stage = sm + OFF_STAGE;
    __half* rowmn = sm + OFF_ROWMN;
    __half* m2d   = sm + OFF_M2D;
    __half* ero   = sm + OFF_ERO;
    __half* rmax  = sm + OFF_RMAX;
    __half* e2d   = sm + OFF_E2D;

    const __half* src = flip ? g_Xp2 : g_Xp;
    __half*       dst = flip ? g_Xp  : g_Xp2;

    int tid = threadIdx.x;
    int r = bi;
    int b = r / 250; r %= 250;
    int zc = r / 25; int t = r % 25;
    int h0 = (t / 5) * 32, w0 = (t % 5) * 32;
    int z0 = zc * 16;
    int base = b * SVOL;

    // one-time pad fill (both stage buffers, cols 0..5 and 42..47 stay +inf)
    for (int i = tid; i < 864; i += 256) {
        int s = i / 432, j = i % 432;
        int row = j / 12, c = j % 12;
        stage[s * 1728 + row * 48 + ((c < 6) ? c : c + 36)] = HPINF;
    }

    for (int zb = z0 - 2; zb <= z0 + 16; zb += 2) {
        // ---- A: stage x slices zb, zb+1 ----
        for (int i = tid; i < 576; i += 256) {
            int s = i / 288, j = i % 288;
            int row = j >> 3, qw = j & 7;
            int zl = zb + s;
            int h = h0 + row - 2;
            h4 v = h4fill(HPINF);
            if ((unsigned)zl < 160u && (unsigned)h < 160u)
                v = *(const h4*)(src + base + (zl * 160 + h) * 160 + w0 + qw * 4);
            *(h4*)&stage[s * 1728 + row * 48 + 8 + qw * 4] = v;
        }
        for (int i = tid; i < 288; i += 256) {            // halos w in {-2,-1,32,33}
            int s = i / 144, j = i % 144;
            int row = j >> 2, k = j & 3;
            int w = (k < 2) ? (k - 2) : (k + 30);
            int zl = zb + s;
            int h = h0 + row - 2, ww = w0 + w;
            __half v = HPINF;
            if ((unsigned)zl < 160u && (unsigned)h < 160u && (unsigned)ww < 160u)
                v = src[base + (zl * 160 + h) * 160 + ww];
            stage[s * 1728 + row * 48 + 8 + w] = v;
        }
        __syncthreads();
        // ---- B: row-min along w (both slices) ----
        for (int i = tid; i < 720; i += 256) {
            int s = i / 360, j = i % 360;
            int g = j % 10, row = j / 10;
            const __half* sp = &stage[s * 1728 + row * 48 + 4 + g * 4];
            h4 o = shiftMin(sp[-1], *(const h4*)sp, sp[4]);
            *(h4*)&rowmn[s * 1440 + row * 40 + g * 4] = o;
        }
        __syncthreads();
        // ---- C: col-min -> m2d[zb], m2d[zb+1]; z-min -> ero[zb-1], ero[zb] ----
        int mA = (zb + 6) & 3, mB = (zb + 7) & 3;       // slots zb-2, zb-1
        int m0 = (zb + 8) & 3, m1 = (zb + 9) & 3;       // slots zb,   zb+1
        int e0s = (zb + 8) % 3, e1s = (zb + 9) % 3;     // ero slots zb-1, zb
        bool zv0 = ((unsigned)(zb - 1) < 160u);
        bool zv1 = ((unsigned)zb < 160u);
        for (int i = tid; i < 340; i += 256) {
            int g = i % 10, mrow = i / 10;
            int off = mrow * 40 + g * 4;
            h4 v0, v1;
            {
                h4 r0 = *(h4*)&rowmn[off];
                h4 r1 = *(h4*)&rowmn[off + 40];
                h4 r2 = *(h4*)&rowmn[off + 80];
                v0 = h4min3(r0, r1, r2);
            }
            {
                h4 r0 = *(h4*)&rowmn[1440 + off];
                h4 r1 = *(h4*)&rowmn[1440 + off + 40];
                h4 r2 = *(h4*)&rowmn[1440 + off + 80];
                v1 = h4min3(r0, r1, r2);
            }
            *(h4*)&m2d[m0 * 1360 + off] = v0;
            *(h4*)&m2d[m1 * 1360 + off] = v1;
            h4 ma = *(h4*)&m2d[mA * 1360 + off];
            h4 mb = *(h4*)&m2d[mB * 1360 + off];
            h4 eA = zv0 ? h4min3(ma, mb, v0) : h4fill(HNINF);
            h4 eB = zv1 ? h4min3(mb, v0, v1) : h4fill(HNINF);
            *(h4*)&ero[e0s * 1360 + off] = eA;
            *(h4*)&ero[e1s * 1360 + off] = eB;
        }
        __syncthreads();
        // ---- D: row-max of ero[zb-1], ero[zb] ----
        for (int i = tid; i < 544; i += 256) {
            int s = i / 272, j = i % 272;
            int g = j & 7, row = j >> 3;
            int es = s ? e1s : e0s;
            const __half* ep = &ero[es * 1360 + row * 40 + 4 + g * 4];
            h4 o = shiftMax(ep[-1], *(const h4*)ep, ep[4]);
            *(h4*)&rmax[s * 1088 + row * 32 + g * 4] = o;
        }
        __syncthreads();
        // ---- E+F fused: col-max -> e2d[zb-1], e2d[zb]; outputs z = zb-2, zb-1 ----
        {
            int g = tid & 7, h = tid >> 3;     // exactly 256 items
            int off = h * 32 + g * 4;
            h4 v0, v1;
            {
                h4 r0 = *(h4*)&rmax[off];
                h4 r1 = *(h4*)&rmax[off + 32];
                h4 r2 = *(h4*)&rmax[off + 64];
                v0 = h4max3(r0, r1, r2);       // e2d[zb-1]
            }
            {
                h4 r0 = *(h4*)&rmax[1088 + off];
                h4 r1 = *(h4*)&rmax[1088 + off + 32];
                h4 r2 = *(h4*)&rmax[1088 + off + 64];
                v1 = h4max3(r0, r1, r2);       // e2d[zb]
            }
            *(h4*)&e2d[((zb + 7) & 3) * 1024 + off] = v0;
            *(h4*)&e2d[((zb + 8) & 3) * 1024 + off] = v1;

            int za = zb - 2;
            if (za >= z0) {
                __half2 z2 = __float2half2_rn(0.0f);
                // output za = zb-2: e2d slices za-1, za, za+1=v0
                {
                    h4 ea = *(h4*)&e2d[((zb + 5) & 3) * 1024 + off];   // e2d[zb-3]
                    h4 eb = *(h4*)&e2d[((zb + 6) & 3) * 1024 + off];   // e2d[zb-2]
                    h4 op = h4max3(ea, eb, v0);
                    h4 er = *(h4*)&ero[((zb + 7) % 3) * 1360 + (h + 1) * 40 + 4 + g * 4];
                    h4 xv = *(const h4*)(src + base + (za * 160 + h0 + h) * 160 + w0 + g * 4);
                    h4 o;
                    o.a = __hmax2(__hsub2(xv.a, __hmax2(__hsub2(op.a, er.a), z2)), z2);
                    o.b = __hmax2(__hsub2(xv.b, __hmax2(__hsub2(op.b, er.b), z2)), z2);
                    *(h4*)(dst + base + (za * 160 + h0 + h) * 160 + w0 + g * 4) = o;
                }
                // output zB = zb-1: e2d slices zb-2, zb-1=v0, zb=v1
                {
                    int zB = zb - 1;
                    h4 eb = *(h4*)&e2d[((zb + 6) & 3) * 1024 + off];
                    h4 op = h4max3(eb, v0, v1);
                    h4 er = *(h4*)&ero[e0s * 1360 + (h + 1) * 40 + 4 + g * 4];
                    h4 xv = *(const h4*)(src + base + (zB * 160 + h0 + h) * 160 + w0 + g * 4);
                    h4 o;
                    o.a = __hmax2(__hsub2(xv.a, __hmax2(__hsub2(op.a, er.a), z2)), z2);
                    o.b = __hmax2(__hsub2(xv.b, __hmax2(__hsub2(op.b, er.b), z2)), z2);
                    *(h4*)(dst + base + (zB * 160 + h0 + h) * 160 + w0 + g * 4) = o;
                }
            }
        }
        // no trailing sync: every cross-step hazard has >=1 barrier in between
    }
}

// Bit-domain y skeleton: 3 phases/slice, chunk 4. (verified R6-R10)
__device__ __forceinline__ void y_skel_block(unsigned int* su, int bi2, int flip) {
    unsigned int* X  = su + YOFF_X;
    unsigned int* WH = su + YOFF_WH;   // ring3
    unsigned int* E  = su + YOFF_E;    // ring2
    unsigned int* D  = su + YOFF_D;    // ring3

    const unsigned int* src = flip ? g_Yb2 : g_Yb;
    unsigned int*       dst = flip ? g_Yb  : g_Yb2;

    int tid = threadIdx.x;
    int b = bi2 / 40, c = bi2 % 40;
    int z0 = c * 4, z1 = z0 + 3;
    int gbase = b * WBAT;

    for (int zl = z0 - 2; zl <= z1 + 2; ++zl) {
        {
            bool zok = ((unsigned)zl < 160u);
            for (int i = tid; i < 800; i += 256)
                X[i] = zok ? src[gbase + zl * 800 + i] : 0xFFFFFFFFu;
        }
        __syncthreads();
        {
            int wsW = (zl + 6) % 3;
            int wA = (zl + 4) % 3, wB = (zl + 5) % 3;
            int esW = (zl + 7) & 1;
            bool zev = ((unsigned)(zl - 1) < 160u);
            for (int i = tid; i < 800; i += 256) {
                int rr = i / W5, j = i - rr * W5;
                unsigned acc = 0xFFFFFFFFu;
#pragma unroll
                for (int d = -1; d <= 1; d++) {
                    int row = rr + d;
                    if ((unsigned)row < 160u) {
                        int bi_ = row * W5 + j;
                        unsigned w = X[bi_];
                        unsigned l = j > 0 ? X[bi_ - 1] : 0xFFFFFFFFu;
                        unsigned rg = j < 4 ? X[bi_ + 1] : 0xFFFFFFFFu;
                        acc &= w & ((w << 1) | (l >> 31)) & ((w >> 1) | (rg << 31));
                    }
                }
                unsigned e = WH[wA * 800 + i] & WH[wB * 800 + i] & acc;
                WH[wsW * 800 + i] = acc;
                E[esW * 800 + i] = zev ? e : 0u;
            }
        }
        __syncthreads();
        {
            int esR = (zl + 7) & 1;
            int dW = (zl + 5) % 3;
            int dA = (zl + 3) % 3, dB = (zl + 4) % 3;
            int z = zl - 2;
            int ezC = (zl + 6) & 1;
            for (int i = tid; i < 800; i += 256) {
                int rr = i / W5, j = i - rr * W5;
                unsigned acc = 0u;
#pragma unroll
                for (int d = -1; d <= 1; d++) {
                    int row = rr + d;
                    if ((unsigned)row < 160u) {
                        int bi_ = esR * 800 + row * W5 + j;
                        unsigned w = E[bi_];
                        unsigned l = j > 0 ? E[bi_ - 1] : 0u;
                        unsigned rg = j < 4 ? E[bi_ + 1] : 0u;
                        acc |= w | (w << 1) | (l >> 31) | (w >> 1) | (rg << 31);
                    }
                }
                D[dW * 800 + i] = acc;
                if (z >= z0) {
                    unsigned open = D[dA * 800 + i] | D[dB * 800 + i] | acc;
                    unsigned x = src[gbase + z * 800 + i];
                    dst[gbase + z * 800 + i] = x & (~open | E[ezC * 800 + i]);
                }
            }
        }
    }
}

__global__ void __launch_bounds__(256, 4) k_skel(int flip) {
    extern __shared__ __half smh[];
    int bi = blockIdx.x;
    if (bi < 500) p_skel_block(smh, bi, flip);
    else          y_skel_block((unsigned int*)smh, bi - 500, flip);
}

__global__ void __launch_bounds__(256) k_cl_reduce() {
    int q = blockIdx.x * 256 + threadIdx.x;
    h4 psh = ((const h4*)g_Xp)[q];
    float2 p01 = __half22float2(psh.a);
    float2 p23 = __half22float2(psh.b);
    h4 poh = ((const h4*)g_Porig)[q];
    float2 o01 = __half22float2(poh.a);
    float2 o23 = __half22float2(poh.b);
    unsigned wS = g_Yb[q >> 3];
    unsigned wO = g_Yb0[q >> 3];
    int sh = (q & 7) * 4;
    unsigned ns = (wS >> sh) & 0xFu;
    unsigned no = (wO >> sh) & 0xFu;
    float ys0 = (float)(ns & 1),        ys1 = (float)((ns >> 1) & 1);
    float ys2 = (float)((ns >> 2) & 1), ys3 = (float)((ns >> 3) & 1);
    float yo0 = (float)(no & 1),        yo1 = (float)((no >> 1) & 1);
    float yo2 = (float)((no >> 2) & 1), yo3 = (float)((no >> 3) & 1);
    float sp  = p01.x + p01.y + p23.x + p23.y;
    float spy = p01.x * yo0 + p01.y * yo1 + p23.x * yo2 + p23.y * yo3;
    float sy  = ys0 + ys1 + ys2 + ys3;
    float syp = ys0 * o01.x + ys1 * o01.y + ys2 * o23.x + ys3 * o23.y;
    float vals[4] = {sp, spy, sy, syp};
    blockAddTo<4>(vals, g_acc + 10);
}

__global__ void k_fin(float* out) {
    double ce = g_acc[0] / (double)NTOT;
    double dsum = 0.0;
#pragma unroll
    for (int c = 0; c < 3; c++) {
        double I = g_acc[1 + c], P = g_acc[4 + c], T = g_acc[7 + c];
        dsum += (2.0 * I + 1e-5) / (P + T + 1e-5);
    }
    double base = ce + (1.0 - dsum / 3.0);
    double tprec = g_acc[11] / (g_acc[10] + 1e-6);
    double tsens = g_acc[13] / (g_acc[12] + 1e-6);
    double cl = 2.0 * tprec * tsens / (tprec + tsens + 1e-6);
    out[0] = (float)(base + 0.5 * (1.0 - cl));
}

extern "C" void kernel_launch(void* const* d_in, const int* in_sizes, int n_in,
                              void* d_out, int out_size) {
    const float* logits = (const float*)d_in[0];
    const int* target = (const int*)d_in[1];

    cudaFuncSetAttribute((const void*)k_skel,
                         cudaFuncAttributeMaxDynamicSharedMemorySize, SM_BYTES);

    k_zero<<<1, 32>>>();
    k_init<<<NQ / 256, 256>>>(logits, target);
    for (int it = 0; it < 8; ++it)
        k_skel<<<580, 256, SM_BYTES>>>(it & 1);
    k_cl_reduce<<<NQ / 256, 256>>>();
    k_fin<<<1, 1>>>((float*)d_out);
}

// round 12
// speedup vs baseline: 1.1972x; 1.1972x over previous
#include <cuda_runtime.h>
#include <cuda_fp16.h>

#define SVOL  4096000        // 160^3
#define NTOT  8192000        // 2 * 160^3
#define NQ    2048000        // NTOT / 4

// ---- p skeleton smem layout (halves), tile 32x32, zchunk 16, 2 z-slices per iter ----
#define OFF_STAGE 0          // 2 x [36][48]   (stride 1728)
#define OFF_ROWMN 3456       // 2 x [36][40]   (stride 1440)
#define OFF_M2D   6336       // ring4 [34][40] (stride 1360)
#define OFF_ERO   11776      // ring3 [34][40] (stride 1360)
#define OFF_RMAX  15856      // 2 x [34][32]   (stride 1088)
#define OFF_E2D   18032      // ring4 [32][32] (stride 1024)
#define SM_HALVES 22128
#define SM_BYTES  (SM_HALVES * 2)   // 44256

// ---- y bit skeleton smem layout (words) — R6 6-phase version ----
#define W5    5
#define WSL   800
#define WBAT  128000
#define YW    256000
#define YOFF_X   0           // [800]
#define YOFF_WT  800         // [800] transient (w-erode / w-dilate)
#define YOFF_WH  1600        // ring3 [800]
#define YOFF_E   4000        // ring2 [800]
#define YOFF_D   5600        // ring3 [800]
// y total 8000 words = 32000 B < SM_BYTES

#define HPINF __ushort_as_half((unsigned short)0x7C00)
#define HNINF __ushort_as_half((unsigned short)0xFC00)

struct __align__(8) h4 { __half2 a, b; };

__device__ double g_acc[14];
__device__ __half g_Xp[NTOT];
__device__ __half g_Xp2[NTOT];
__device__ __half g_Porig[NTOT];
__device__ unsigned int g_Yb0[YW];
__device__ unsigned int g_Yb[YW];
__device__ unsigned int g_Yb2[YW];

__device__ __forceinline__ h4 h4fill(__half v) {
    h4 o; o.a = __half2half2(v); o.b = o.a; return o;
}
__device__ __forceinline__ h4 h4min3(h4 x, h4 y, h4 z) {
    h4 o;
    o.a = __hmin2(x.a, __hmin2(y.a, z.a));
    o.b = __hmin2(x.b, __hmin2(y.b, z.b));
    return o;
}
__device__ __forceinline__ h4 h4max3(h4 x, h4 y, h4 z) {
    h4 o;
    o.a = __hmax2(x.a, __hmax2(y.a, z.a));
    o.b = __hmax2(x.b, __hmax2(y.b, z.b));
    return o;
}
__device__ __forceinline__ h4 shiftMin(__half l, h4 c, __half r) {
    __half2 sl  = __halves2half2(l, __low2half(c.a));
    __half2 sr  = __halves2half2(__high2half(c.a), __low2half(c.b));
    __half2 sr2 = __halves2half2(__high2half(c.b), r);
    h4 o;
    o.a = __hmin2(__hmin2(sl, c.a), sr);
    o.b = __hmin2(__hmin2(sr, c.b), sr2);
    return o;
}
__device__ __forceinline__ h4 shiftMax(__half l, h4 c, __half r) {
    __half2 sl  = __halves2half2(l, __low2half(c.a));
    __half2 sr  = __halves2half2(__high2half(c.a), __low2half(c.b));
    __half2 sr2 = __halves2half2(__high2half(c.b), r);
    h4 o;
    o.a = __hmax2(__hmax2(sl, c.a), sr);
    o.b = __hmax2(__hmax2(sr, c.b), sr2);
    return o;
}

template <int NV>
__device__ __forceinline__ void blockAddTo(const float* vals, double* gout) {
    __shared__ float red[NV][8];
    int tid = threadIdx.x, lane = tid & 31, w = tid >> 5;
#pragma unroll
    for (int k = 0; k < NV; k++) {
        float v = vals[k];
#pragma unroll
        for (int o = 16; o; o >>= 1) v += __shfl_down_sync(0xffffffffu, v, o);
        if (lane == 0) red[k][w] = v;
    }
    __syncthreads();
    if (w == 0) {
#pragma unroll
        for (int k = 0; k < NV; k++) {
            float v = (lane < 8) ? red[k][lane] : 0.0f;
#pragma unroll
            for (int o = 4; o; o >>= 1) v += __shfl_down_sync(0xffffffffu, v, o);
            if (lane == 0) atomicAdd(&gout[k], (double)v);
        }
    }
}

__global__ void k_zero() {
    if (threadIdx.x < 14) g_acc[threadIdx.x] = 0.0;
}

__global__ void __launch_bounds__(256) k_init(const float* __restrict__ logits,
                                              const int* __restrict__ target) {
    __shared__ unsigned char nib[256];
    int tid = threadIdx.x;
    int q = blockIdx.x * 256 + tid;
    int e = q * 4;
    int b = (e >= SVOL) ? 1 : 0;
    int s = e - b * SVOL;
    const float* lp = logits + (size_t)b * 3 * SVOL + s;
    float4 L0 = *(const float4*)(lp);
    float4 L1 = *(const float4*)(lp + SVOL);
    float4 L2 = *(const float4*)(lp + 2 * SVOL);
    int4 ti = ((const int4*)target)[q];
    int tg[4] = {ti.x, ti.y, ti.z, ti.w};
    float a0[4] = {L0.x, L0.y, L0.z, L0.w};
    float a1[4] = {L1.x, L1.y, L1.z, L1.w};
    float a2[4] = {L2.x, L2.y, L2.z, L2.w};

    float ce = 0.f, i0 = 0.f, i1 = 0.f, i2 = 0.f;
    float s0 = 0.f, s1 = 0.f, s2 = 0.f, c0 = 0.f, c1 = 0.f, c2 = 0.f;
    float pv[4];
    unsigned nb = 0;
#pragma unroll
    for (int j = 0; j < 4; j++) {
        float x0 = a0[j], x1 = a1[j], x2 = a2[j];
        float m = fmaxf(x0, fmaxf(x1, x2));
        float e0 = __expf(x0 - m), e1 = __expf(x1 - m), e2 = __expf(x2 - m);
        float sum = e0 + e1 + e2;
        float inv = 1.0f / sum;
        float p0 = e0 * inv, p1 = e1 * inv, p2 = e2 * inv;
        float ls = __logf(sum);
        int t = tg[j];
        float lt = (t == 0) ? x0 : ((t == 1) ? x1 : x2);
        ce += (m + ls - lt);
        s0 += p0; s1 += p1; s2 += p2;
        if (t == 0)      { i0 += p0; c0 += 1.f; }
        else if (t == 1) { i1 += p1; c1 += 1.f; }
        else             { i2 += p2; c2 += 1.f; }
        pv[j] = fminf(fmaxf(1.0f - p0, 0.0f), 1.0f);
        if (t != 0) nb |= (1u << j);
    }
    h4 PV;
    PV.a = __floats2half2_rn(pv[0], pv[1]);
    PV.b = __floats2half2_rn(pv[2], pv[3]);
    ((h4*)g_Xp)[q] = PV;
    ((h4*)g_Porig)[q] = PV;
    nib[tid] = (unsigned char)nb;
    __syncthreads();
    if (tid < 32) {
        unsigned w = 0;
#pragma unroll
        for (int k = 0; k < 8; k++) w |= ((unsigned)nib[tid * 8 + k]) << (4 * k);
        int wi = blockIdx.x * 32 + tid;
        g_Yb0[wi] = w;
        g_Yb[wi] = w;
    }

    float vals[10] = {ce, i0, i1, i2, s0, s1, s2, c0, c1, c2};
    blockAddTo<10>(vals, g_acc);
}

// ---------------- merged skeleton iteration -----------------
// blocks [0,500): fp16 p skeleton (tile 32x32, zchunk 16, 2 slices/iter).
// blocks [500,580): bit y skeleton (chunk 4, 6-phase separable — R6 version).

__device__ __forceinline__ void p_skel_block(__half* sm, int bi, int flip) {
    __half* stage = sm + OFF_STAGE;
    __half* rowmn = sm + OFF_ROWMN;
    __half* m2d   = sm + OFF_M2D;
    __half* ero   = sm + OFF_ERO;
    __half* rmax  = sm + OFF_RMAX;
    __half* e2d   = sm + OFF_E2D;

    const __half* src = flip ? g_Xp2 : g_Xp;
    __half*       dst = flip ? g_Xp  : g_Xp2;

    int tid = threadIdx.x;
    int r = bi;
    int b = r / 250; r %= 250;
    int zc = r / 25; int t = r % 25;
    int h0 = (t / 5) * 32, w0 = (t % 5) * 32;
    int z0 = zc * 16;
    int base = b * SVOL;

    // one-time pad fill (both stage buffers, cols 0..5 and 42..47 stay +inf)
    for (int i = tid; i < 864; i += 256) {
        int s = i / 432, j = i % 432;
        int row = j / 12, c = j % 12;
        stage[s * 1728 + row * 48 + ((c < 6) ? c : c + 36)] = HPINF;
    }

    for (int zb = z0 - 2; zb <= z0 + 16; zb += 2) {
        // ---- A: stage x slices zb, zb+1 ----
        for (int i = tid; i < 576; i += 256) {
            int s = i / 288, j = i % 288;
            int row = j >> 3, qw = j & 7;
            int zl = zb + s;
            int h = h0 + row - 2;
            h4 v = h4fill(HPINF);
            if ((unsigned)zl < 160u && (unsigned)h < 160u)
                v = *(const h4*)(src + base + (zl * 160 + h) * 160 + w0 + qw * 4);
            *(h4*)&stage[s * 1728 + row * 48 + 8 + qw * 4] = v;
        }
        for (int i = tid; i < 288; i += 256) {            // halos w in {-2,-1,32,33}
            int s = i / 144, j = i % 144;
            int row = j >> 2, k = j & 3;
            int w = (k < 2) ? (k - 2) : (k + 30);
            int zl = zb + s;
            int h = h0 + row - 2, ww = w0 + w;
            __half v = HPINF;
            if ((unsigned)zl < 160u && (unsigned)h < 160u && (unsigned)ww < 160u)
                v = src[base + (zl * 160 + h) * 160 + ww];
            stage[s * 1728 + row * 48 + 8 + w] = v;
        }
        __syncthreads();
        // ---- B: row-min along w (both slices) ----
        for (int i = tid; i < 720; i += 256) {
            int s = i / 360, j = i % 360;
            int g = j % 10, row = j / 10;
            const __half* sp = &stage[s * 1728 + row * 48 + 4 + g * 4];
            h4 o = shiftMin(sp[-1], *(const h4*)sp, sp[4]);
            *(h4*)&rowmn[s * 1440 + row * 40 + g * 4] = o;
        }
        __syncthreads();
        // ---- C: col-min -> m2d[zb], m2d[zb+1]; z-min -> ero[zb-1], ero[zb] ----
        int mA = (zb + 6) & 3, mB = (zb + 7) & 3;       // slots zb-2, zb-1
        int m0 = (zb + 8) & 3, m1 = (zb + 9) & 3;       // slots zb,   zb+1
        int e0s = (zb + 8) % 3, e1s = (zb + 9) % 3;     // ero slots zb-1, zb
        bool zv0 = ((unsigned)(zb - 1) < 160u);
        bool zv1 = ((unsigned)zb < 160u);
        for (int i = tid; i < 340; i += 256) {
            int g = i % 10, mrow = i / 10;
            int off = mrow * 40 + g * 4;
            h4 v0, v1;
            {
                h4 r0 = *(h4*)&rowmn[off];
                h4 r1 = *(h4*)&rowmn[off + 40];
                h4 r2 = *(h4*)&rowmn[off + 80];
                v0 = h4min3(r0, r1, r2);
            }
            {
                h4 r0 = *(h4*)&rowmn[1440 + off];
                h4 r1 = *(h4*)&rowmn[1440 + off + 40];
                h4 r2 = *(h4*)&rowmn[1440 + off + 80];
                v1 = h4min3(r0, r1, r2);
            }
            *(h4*)&m2d[m0 * 1360 + off] = v0;
            *(h4*)&m2d[m1 * 1360 + off] = v1;
            h4 ma = *(h4*)&m2d[mA * 1360 + off];
            h4 mb = *(h4*)&m2d[mB * 1360 + off];
            h4 eA = zv0 ? h4min3(ma, mb, v0) : h4fill(HNINF);
            h4 eB = zv1 ? h4min3(mb, v0, v1) : h4fill(HNINF);
            *(h4*)&ero[e0s * 1360 + off] = eA;
            *(h4*)&ero[e1s * 1360 + off] = eB;
        }
        __syncthreads();
        // ---- D: row-max of ero[zb-1], ero[zb] ----
        for (int i = tid; i < 544; i += 256) {
            int s = i / 272, j = i % 272;
            int g = j & 7, row = j >> 3;
            int es = s ? e1s : e0s;
            const __half* ep = &ero[es * 1360 + row * 40 + 4 + g * 4];
            h4 o = shiftMax(ep[-1], *(const h4*)ep, ep[4]);
            *(h4*)&rmax[s * 1088 + row * 32 + g * 4] = o;
        }
        __syncthreads();
        // ---- E+F fused: col-max -> e2d[zb-1], e2d[zb]; outputs z = zb-2, zb-1 ----
        {
            int g = tid & 7, h = tid >> 3;     // exactly 256 items
            int off = h * 32 + g * 4;
            h4 v0, v1;
            {
                h4 r0 = *(h4*)&rmax[off];
                h4 r1 = *(h4*)&rmax[off + 32];
                h4 r2 = *(h4*)&rmax[off + 64];
                v0 = h4max3(r0, r1, r2);       // e2d[zb-1]
            }
            {
                h4 r0 = *(h4*)&rmax[1088 + off];
                h4 r1 = *(h4*)&rmax[1088 + off + 32];
                h4 r2 = *(h4*)&rmax[1088 + off + 64];
                v1 = h4max3(r0, r1, r2);       // e2d[zb]
            }
            *(h4*)&e2d[((zb + 7) & 3) * 1024 + off] = v0;
            *(h4*)&e2d[((zb + 8) & 3) * 1024 + off] = v1;

            int za = zb - 2;
            if (za >= z0) {
                __half2 z2 = __float2half2_rn(0.0f);
                // output za = zb-2: e2d slices za-1, za, za+1=v0
                {
                    h4 ea = *(h4*)&e2d[((zb + 5) & 3) * 1024 + off];   // e2d[zb-3]
                    h4 eb = *(h4*)&e2d[((zb + 6) & 3) * 1024 + off];   // e2d[zb-2]
                    h4 op = h4max3(ea, eb, v0);
                    h4 er = *(h4*)&ero[((zb + 7) % 3) * 1360 + (h + 1) * 40 + 4 + g * 4];
                    h4 xv = *(const h4*)(src + base + (za * 160 + h0 + h) * 160 + w0 + g * 4);
                    h4 o;
                    o.a = __hmax2(__hsub2(xv.a, __hmax2(__hsub2(op.a, er.a), z2)), z2);
                    o.b = __hmax2(__hsub2(xv.b, __hmax2(__hsub2(op.b, er.b), z2)), z2);
                    *(h4*)(dst + base + (za * 160 + h0 + h) * 160 + w0 + g * 4) = o;
                }
                // output zB = zb-1: e2d slices zb-2, zb-1=v0, zb=v1
                {
                    int zB = zb - 1;
                    h4 eb = *(h4*)&e2d[((zb + 6) & 3) * 1024 + off];
                    h4 op = h4max3(eb, v0, v1);
                    h4 er = *(h4*)&ero[e0s * 1360 + (h + 1) * 40 + 4 + g * 4];
                    h4 xv = *(const h4*)(src + base + (zB * 160 + h0 + h) * 160 + w0 + g * 4);
                    h4 o;
                    o.a = __hmax2(__hsub2(xv.a, __hmax2(__hsub2(op.a, er.a), z2)), z2);
                    o.b = __hmax2(__hsub2(xv.b, __hmax2(__hsub2(op.b, er.b), z2)), z2);
                    *(h4*)(dst + base + (zB * 160 + h0 + h) * 160 + w0 + g * 4) = o;
                }
            }
        }
        // no trailing sync: every cross-step hazard has >=1 barrier in between
    }
}

// Bit-domain y skeleton, 4 output slices per block, 6-phase separable (R6 version).
__device__ __forceinline__ void y_skel_block(unsigned int* su, int bi2, int flip) {
    unsigned int* X  = su + YOFF_X;
    unsigned int* WT = su + YOFF_WT;
    unsigned int* WH = su + YOFF_WH;   // ring3
    unsigned int* E  = su + YOFF_E;    // ring2
    unsigned int* D  = su + YOFF_D;    // ring3

    const unsigned int* src = flip ? g_Yb2 : g_Yb;
    unsigned int*       dst = flip ? g_Yb  : g_Yb2;

    int tid = threadIdx.x;
    int b = bi2 / 40, c = bi2 % 40;
    int z0 = c * 4, z1 = z0 + 3;
    int gbase = b * WBAT;

    for (int zl = z0 - 2; zl <= z1 + 2; ++zl) {
        // P1: load X slice zl (OOB = all ones)
        {
            bool zok = ((unsigned)zl < 160u);
            for (int i = tid; i < 800; i += 256)
                X[i] = zok ? src[gbase + zl * 800 + i] : 0xFFFFFFFFu;
        }
        __syncthreads();
        // P2: w-erode X -> WT
        for (int i = tid; i < 800; i += 256) {
            int j = i % W5;
            unsigned w = X[i];
            unsigned l = j > 0 ? X[i - 1] : 0xFFFFFFFFu;
            unsigned r = j < 4 ? X[i + 1] : 0xFFFFFFFFu;
            WT[i] = w & ((w << 1) | (l >> 31)) & ((w >> 1) | (r << 31));
        }
        __syncthreads();
        // P3: h-erode WT -> WH[zl]
        {
            int ws = (zl + 6) % 3;
            for (int i = tid; i < 800; i += 256) {
                int r = i / W5;
                unsigned w = WT[i];
                unsigned up = r > 0   ? WT[i - W5] : 0xFFFFFFFFu;
                unsigned dn = r < 159 ? WT[i + W5] : 0xFFFFFFFFu;
                WH[ws * 800 + i] = w & up & dn;
            }
        }
        __syncthreads();
        // P4: z-erode -> E[zl-1] (OOB slice -> 0)
        int ze = zl - 1;
        int es = (ze + 2) & 1;
        {
            bool zev = ((unsigned)ze < 160u);
            int wa = (ze + 5) % 3, wb = (ze + 6) % 3, wc = (ze + 7) % 3;
            for (int i = tid; i < 800; i += 256) {
                unsigned e = WH[wa * 800 + i] & WH[wb * 800 + i] & WH[wc * 800 + i];
                E[es * 800 + i] = zev ? e : 0u;
            }
        }
        __syncthreads();
        // P5: w-dilate E[zl-1] -> WT
        for (int i = tid; i < 800; i += 256) {
            int j = i % W5;
            unsigned w = E[es * 800 + i];
            unsigned l = j > 0 ? E[es * 800 + i - 1] : 0u;
            unsigned r = j < 4 ? E[es * 800 + i + 1] : 0u;
            WT[i] = w | (w << 1) | (l >> 31) | (w >> 1) | (r << 31);
        }
        __syncthreads();
        // P6: h-dilate WT -> D[zl-1]
        {
            int ds = (ze + 6) % 3;
            for (int i = tid; i < 800; i += 256) {
                int r = i / W5;
                unsigned w = WT[i];
                unsigned up = r > 0   ? WT[i - W5] : 0u;
                unsigned dn = r < 159 ? WT[i + W5] : 0u;
                D[ds * 800 + i] = w | up | dn;
            }
        }
        __syncthreads();
        // P7: combine at z = zl-2, x re-read from global
        int z = zl - 2;
        if (z >= z0) {
            int da = (z + 5) % 3, db = (z + 6) % 3, dc = (z + 7) % 3;
            int ez = (z + 2) & 1;
            for (int i = tid; i < 800; i += 256) {
                unsigned open = D[da * 800 + i] | D[db * 800 + i] | D[dc * 800 + i];
                unsigned x = src[gbase + z * 800 + i];
                dst[gbase + z * 800 + i] = x & (~open | E[ez * 800 + i]);
            }
        }
    }
}

__global__ void __launch_bounds__(256, 4) k_skel(int flip) {
    extern __shared__ __half smh[];
    int bi = blockIdx.x;
    if (bi < 500) p_skel_block(smh, bi, flip);
    else          y_skel_block((unsigned int*)smh, bi - 500, flip);
}

__global__ void __launch_bounds__(256) k_cl_reduce() {
    int q = blockIdx.x * 256 + threadIdx.x;
    h4 psh = ((const h4*)g_Xp)[q];
    float2 p01 = __half22float2(psh.a);
    float2 p23 = __half22float2(psh.b);
    h4 poh = ((const h4*)g_Porig)[q];
    float2 o01 = __half22float2(poh.a);
    float2 o23 = __half22float2(poh.b);
    unsigned wS = g_Yb[q >> 3];
    unsigned wO = g_Yb0[q >> 3];
    int sh = (q & 7) * 4;
    unsigned ns = (wS >> sh) & 0xFu;
    unsigned no = (wO >> sh) & 0xFu;
    float ys0 = (float)(ns & 1),        ys1 = (float)((ns >> 1) & 1);
    float ys2 = (float)((ns >> 2) & 1), ys3 = (float)((ns >> 3) & 1);
    float yo0 = (float)(no & 1),        yo1 = (float)((no >> 1) & 1);
    float yo2 = (float)((no >> 2) & 1), yo3 = (float)((no >> 3) & 1);
    float sp  = p01.x + p01.y + p23.x + p23.y;
    float spy = p01.x * yo0 + p01.y * yo1 + p23.x * yo2 + p23.y * yo3;
    float sy  = ys0 + ys1 + ys2 + ys3;
    float syp = ys0 * o01.x + ys1 * o01.y + ys2 * o23.x + ys3 * o23.y;
    float vals[4] = {sp, spy, sy, syp};
    blockAddTo<4>(vals, g_acc + 10);
}

__global__ void k_fin(float* out) {
    double ce = g_acc[0] / (double)NTOT;
    double dsum = 0.0;
#pragma unroll
    for (int c = 0; c < 3; c++) {
        double I = g_acc[1 + c], P = g_acc[4 + c], T = g_acc[7 + c];
        dsum += (2.0 * I + 1e-5) / (P + T + 1e-5);
    }
    double base = ce + (1.0 - dsum / 3.0);
    double tprec = g_acc[11] / (g_acc[10] + 1e-6);
    double tsens = g_acc[13] / (g_acc[12] + 1e-6);
    double cl = 2.0 * tprec * tsens / (tprec + tsens + 1e-6);
    out[0] = (float)(base + 0.5 * (1.0 - cl));
}

extern "C" void kernel_launch(void* const* d_in, const int* in_sizes, int n_in,
                              void* d_out, int out_size) {
    const float* logits = (const float*)d_in[0];
    const int* target = (const int*)d_in[1];

    cudaFuncSetAttribute((const void*)k_skel,
                         cudaFuncAttributeMaxDynamicSharedMemorySize, SM_BYTES);

    k_zero<<<1, 32>>>();
    k_init<<<NQ / 256, 256>>>(logits, target);
    for (int it = 0; it < 8; ++it)
        k_skel<<<580, 256, SM_BYTES>>>(it & 1);
    k_cl_reduce<<<NQ / 256, 256>>>();
    k_fin<<<1, 1>>>((float*)d_out);
}

// round 13
// speedup vs baseline: 1.2567x; 1.0497x over previous
#include <cuda_runtime.h>
#include <cuda_fp16.h>

#define SVOL  4096000        // 160^3
#define NTOT  8192000        // 2 * 160^3
#define NQ    2048000        // NTOT / 4

// ---- p skeleton smem layout (halves), tile 32x32, zchunk 16, 2 z-slices per iter ----
#define OFF_STAGE 0          // 2 x [36][48]   (stride 1728)
#define OFF_ROWMN 3456       // 2 x [36][40]   (stride 1440)
#define OFF_M2D   6336       // ring4 [34][40] (stride 1360)
#define OFF_ERO   11776      // ring3 [34][40] (stride 1360)
#define OFF_RMAX  15856      // 2 x [34][32]   (stride 1088)
#define OFF_E2D   18032      // ring4 [32][32] (stride 1024)
#define SM_HALVES 22128
#define SM_BYTES  (SM_HALVES * 2)   // 44256

// ---- y bit skeleton smem layout (words) — 6-phase separable (R6 version) ----
#define W5    5
#define WSL   800
#define WBAT  128000
#define YW    256000
#define YOFF_X   0           // [800]
#define YOFF_WT  800         // [800] transient (w-erode / w-dilate)
#define YOFF_WH  1600        // ring3 [800]
#define YOFF_E   4000        // ring2 [800]
#define YOFF_D   5600        // ring3 [800]
// y total 8000 words = 32000 B < SM_BYTES

#define HPINF __ushort_as_half((unsigned short)0x7C00)
#define HNINF __ushort_as_half((unsigned short)0xFC00)

struct __align__(8) h4 { __half2 a, b; };

__device__ double g_acc[14];
__device__ __half g_Xp[NTOT];
__device__ __half g_Xp2[NTOT];
__device__ __half g_Porig[NTOT];
__device__ unsigned int g_Yb0[YW];
__device__ unsigned int g_Yb[YW];
__device__ unsigned int g_Yb2[YW];

__device__ __forceinline__ h4 h4fill(__half v) {
    h4 o; o.a = __half2half2(v); o.b = o.a; return o;
}
__device__ __forceinline__ h4 h4min3(h4 x, h4 y, h4 z) {
    h4 o;
    o.a = __hmin2(x.a, __hmin2(y.a, z.a));
    o.b = __hmin2(x.b, __hmin2(y.b, z.b));
    return o;
}
__device__ __forceinline__ h4 h4max3(h4 x, h4 y, h4 z) {
    h4 o;
    o.a = __hmax2(x.a, __hmax2(y.a, z.a));
    o.b = __hmax2(x.b, __hmax2(y.b, z.b));
    return o;
}
__device__ __forceinline__ h4 shiftMin(__half l, h4 c, __half r) {
    __half2 sl  = __halves2half2(l, __low2half(c.a));
    __half2 sr  = __halves2half2(__high2half(c.a), __low2half(c.b));
    __half2 sr2 = __halves2half2(__high2half(c.b), r);
    h4 o;
    o.a = __hmin2(__hmin2(sl, c.a), sr);
    o.b = __hmin2(__hmin2(sr, c.b), sr2);
    return o;
}
__device__ __forceinline__ h4 shiftMax(__half l, h4 c, __half r) {
    __half2 sl  = __halves2half2(l, __low2half(c.a));
    __half2 sr  = __halves2half2(__high2half(c.a), __low2half(c.b));
    __half2 sr2 = __halves2half2(__high2half(c.b), r);
    h4 o;
    o.a = __hmax2(__hmax2(sl, c.a), sr);
    o.b = __hmax2(__hmax2(sr, c.b), sr2);
    return o;
}

template <int NV>
__device__ __forceinline__ void blockAddTo(const float* vals, double* gout) {
    __shared__ float red[NV][8];
    int tid = threadIdx.x, lane = tid & 31, w = tid >> 5;
#pragma unroll
    for (int k = 0; k < NV; k++) {
        float v = vals[k];
#pragma unroll
        for (int o = 16; o; o >>= 1) v += __shfl_down_sync(0xffffffffu, v, o);
        if (lane == 0) red[k][w] = v;
    }
    __syncthreads();
    if (w == 0) {
#pragma unroll
        for (int k = 0; k < NV; k++) {
            float v = (lane < 8) ? red[k][lane] : 0.0f;
#pragma unroll
            for (int o = 4; o; o >>= 1) v += __shfl_down_sync(0xffffffffu, v, o);
            if (lane == 0) atomicAdd(&gout[k], (double)v);
        }
    }
}

__global__ void k_zero() {
    if (threadIdx.x < 14) g_acc[threadIdx.x] = 0.0;
}

__global__ void __launch_bounds__(256) k_init(const float* __restrict__ logits,
                                              const int* __restrict__ target) {
    __shared__ unsigned char nib[256];
    int tid = threadIdx.x;
    int q = blockIdx.x * 256 + tid;
    int e = q * 4;
    int b = (e >= SVOL) ? 1 : 0;
    int s = e - b * SVOL;
    const float* lp = logits + (size_t)b * 3 * SVOL + s;
    float4 L0 = *(const float4*)(lp);
    float4 L1 = *(const float4*)(lp + SVOL);
    float4 L2 = *(const float4*)(lp + 2 * SVOL);
    int4 ti = ((const int4*)target)[q];
    int tg[4] = {ti.x, ti.y, ti.z, ti.w};
    float a0[4] = {L0.x, L0.y, L0.z, L0.w};
    float a1[4] = {L1.x, L1.y, L1.z, L1.w};
    float a2[4] = {L2.x, L2.y, L2.z, L2.w};

    float ce = 0.f, i0 = 0.f, i1 = 0.f, i2 = 0.f;
    float s0 = 0.f, s1 = 0.f, s2 = 0.f, c0 = 0.f, c1 = 0.f, c2 = 0.f;
    float pv[4];
    unsigned nb = 0;
#pragma unroll
    for (int j = 0; j < 4; j++) {
        float x0 = a0[j], x1 = a1[j], x2 = a2[j];
        float m = fmaxf(x0, fmaxf(x1, x2));
        float e0 = __expf(x0 - m), e1 = __expf(x1 - m), e2 = __expf(x2 - m);
        float sum = e0 + e1 + e2;
        float inv = 1.0f / sum;
        float p0 = e0 * inv, p1 = e1 * inv, p2 = e2 * inv;
        float ls = __logf(sum);
        int t = tg[j];
        float lt = (t == 0) ? x0 : ((t == 1) ? x1 : x2);
        ce += (m + ls - lt);
        s0 += p0; s1 += p1; s2 += p2;
        if (t == 0)      { i0 += p0; c0 += 1.f; }
        else if (t == 1) { i1 += p1; c1 += 1.f; }
        else             { i2 += p2; c2 += 1.f; }
        pv[j] = fminf(fmaxf(1.0f - p0, 0.0f), 1.0f);
        if (t != 0) nb |= (1u << j);
    }
    h4 PV;
    PV.a = __floats2half2_rn(pv[0], pv[1]);
    PV.b = __floats2half2_rn(pv[2], pv[3]);
    ((h4*)g_Porig)[q] = PV;          // iteration 0 reads Porig directly; g_Xp written at it=1
    nib[tid] = (unsigned char)nb;
    __syncthreads();
    if (tid < 32) {
        unsigned w = 0;
#pragma unroll
        for (int k = 0; k < 8; k++) w |= ((unsigned)nib[tid * 8 + k]) << (4 * k);
        int wi = blockIdx.x * 32 + tid;
        g_Yb0[wi] = w;
        g_Yb[wi] = w;
    }

    float vals[10] = {ce, i0, i1, i2, s0, s1, s2, c0, c1, c2};
    blockAddTo<10>(vals, g_acc);
}

// ---------------- merged skeleton iteration -----------------
// blocks [0,500): fp16 p skeleton (tile 32x32, zchunk 16, 2 slices/iter).
// blocks [500,580): bit y skeleton (chunk 4, 6-phase separable).
// On it==7, blocks also accumulate the clDice sums (replaces k_cl_reduce).

__device__ __forceinline__ void p_skel_block(__half* sm, int bi, int it) {
    __half* stage = sm + OFF_STAGE;
    __half* rowmn = sm + OFF_ROWMN;
    __half* m2d   = sm + OFF_M2D;
    __half* ero   = sm + OFF_ERO;
    __half* rmax  = sm + OFF_RMAX;
    __half* e2d   = sm + OFF_E2D;

    const __half* src = (it == 0) ? g_Porig : ((it & 1) ? g_Xp2 : g_Xp);
    __half*       dst = (it & 1) ? g_Xp : g_Xp2;
    bool last = (it == 7);

    int tid = threadIdx.x;
    int r = bi;
    int b = r / 250; r %= 250;
    int zc = r / 25; int t = r % 25;
    int h0 = (t / 5) * 32, w0 = (t % 5) * 32;
    int z0 = zc * 16;
    int base = b * SVOL;

    float accS = 0.f, accSY = 0.f;

    // one-time pad fill (both stage buffers, cols 0..5 and 42..47 stay +inf)
    for (int i = tid; i < 864; i += 256) {
        int s = i / 432, j = i % 432;
        int row = j / 12, c = j % 12;
        stage[s * 1728 + row * 48 + ((c < 6) ? c : c + 36)] = HPINF;
    }

    for (int zb = z0 - 2; zb <= z0 + 16; zb += 2) {
        // ---- A: stage x slices zb, zb+1 ----
        for (int i = tid; i < 576; i += 256) {
            int s = i / 288, j = i % 288;
            int row = j >> 3, qw = j & 7;
            int zl = zb + s;
            int h = h0 + row - 2;
            h4 v = h4fill(HPINF);
            if ((unsigned)zl < 160u && (unsigned)h < 160u)
                v = *(const h4*)(src + base + (zl * 160 + h) * 160 + w0 + qw * 4);
            *(h4*)&stage[s * 1728 + row * 48 + 8 + qw * 4] = v;
        }
        for (int i = tid; i < 288; i += 256) {            // halos w in {-2,-1,32,33}
            int s = i / 144, j = i % 144;
            int row = j >> 2, k = j & 3;
            int w = (k < 2) ? (k - 2) : (k + 30);
            int zl = zb + s;
            int h = h0 + row - 2, ww = w0 + w;
            __half v = HPINF;
            if ((unsigned)zl < 160u && (unsigned)h < 160u && (unsigned)ww < 160u)
                v = src[base + (zl * 160 + h) * 160 + ww];
            stage[s * 1728 + row * 48 + 8 + w] = v;
        }
        __syncthreads();
        // ---- B: row-min along w (both slices) ----
        for (int i = tid; i < 720; i += 256) {
            int s = i / 360, j = i % 360;
            int g = j % 10, row = j / 10;
            const __half* sp = &stage[s * 1728 + row * 48 + 4 + g * 4];
            h4 o = shiftMin(sp[-1], *(const h4*)sp, sp[4]);
            *(h4*)&rowmn[s * 1440 + row * 40 + g * 4] = o;
        }
        __syncthreads();
        // ---- C: col-min -> m2d[zb], m2d[zb+1]; z-min -> ero[zb-1], ero[zb] ----
        int mA = (zb + 6) & 3, mB = (zb + 7) & 3;       // slots zb-2, zb-1
        int m0 = (zb + 8) & 3, m1 = (zb + 9) & 3;       // slots zb,   zb+1
        int e0s = (zb + 8) % 3, e1s = (zb + 9) % 3;     // ero slots zb-1, zb
        bool zv0 = ((unsigned)(zb - 1) < 160u);
        bool zv1 = ((unsigned)zb < 160u);
        for (int i = tid; i < 340; i += 256) {
            int g = i % 10, mrow = i / 10;
            int off = mrow * 40 + g * 4;
            h4 v0, v1;
            {
                h4 r0 = *(h4*)&rowmn[off];
                h4 r1 = *(h4*)&rowmn[off + 40];
                h4 r2 = *(h4*)&rowmn[off + 80];
                v0 = h4min3(r0, r1, r2);
            }
            {
                h4 r0 = *(h4*)&rowmn[1440 + off];
                h4 r1 = *(h4*)&rowmn[1440 + off + 40];
                h4 r2 = *(h4*)&rowmn[1440 + off + 80];
                v1 = h4min3(r0, r1, r2);
            }
            *(h4*)&m2d[m0 * 1360 + off] = v0;
            *(h4*)&m2d[m1 * 1360 + off] = v1;
            h4 ma = *(h4*)&m2d[mA * 1360 + off];
            h4 mb = *(h4*)&m2d[mB * 1360 + off];
            h4 eA = zv0 ? h4min3(ma, mb, v0) : h4fill(HNINF);
            h4 eB = zv1 ? h4min3(mb, v0, v1) : h4fill(HNINF);
            *(h4*)&ero[e0s * 1360 + off] = eA;
            *(h4*)&ero[e1s * 1360 + off] = eB;
        }
        __syncthreads();
        // ---- D: row-max of ero[zb-1], ero[zb] ----
        for (int i = tid; i < 544; i += 256) {
            int s = i / 272, j = i % 272;
            int g = j & 7, row = j >> 3;
            int es = s ? e1s : e0s;
            const __half* ep = &ero[es * 1360 + row * 40 + 4 + g * 4];
            h4 o = shiftMax(ep[-1], *(const h4*)ep, ep[4]);
            *(h4*)&rmax[s * 1088 + row * 32 + g * 4] = o;
        }
        __syncthreads();
        // ---- E+F fused: col-max -> e2d[zb-1], e2d[zb]; outputs z = zb-2, zb-1 ----
        {
            int g = tid & 7, h = tid >> 3;     // exactly 256 items
            int off = h * 32 + g * 4;
            h4 v0, v1;
            {
                h4 r0 = *(h4*)&rmax[off];
                h4 r1 = *(h4*)&rmax[off + 32];
                h4 r2 = *(h4*)&rmax[off + 64];
                v0 = h4max3(r0, r1, r2);       // e2d[zb-1]
            }
            {
                h4 r0 = *(h4*)&rmax[1088 + off];
                h4 r1 = *(h4*)&rmax[1088 + off + 32];
                h4 r2 = *(h4*)&rmax[1088 + off + 64];
                v1 = h4max3(r0, r1, r2);       // e2d[zb]
            }
            *(h4*)&e2d[((zb + 7) & 3) * 1024 + off] = v0;
            *(h4*)&e2d[((zb + 8) & 3) * 1024 + off] = v1;

            int za = zb - 2;
            if (za >= z0) {
                __half2 z2 = __float2half2_rn(0.0f);
                // output za = zb-2: e2d slices za-1, za, za+1=v0
                {
                    h4 ea = *(h4*)&e2d[((zb + 5) & 3) * 1024 + off];   // e2d[zb-3]
                    h4 eb = *(h4*)&e2d[((zb + 6) & 3) * 1024 + off];   // e2d[zb-2]
                    h4 op = h4max3(ea, eb, v0);
                    h4 er = *(h4*)&ero[((zb + 7) % 3) * 1360 + (h + 1) * 40 + 4 + g * 4];
                    int vox = base + (za * 160 + h0 + h) * 160 + w0 + g * 4;
                    h4 xv = *(const h4*)(src + vox);
                    h4 o;
                    o.a = __hmax2(__hsub2(xv.a, __hmax2(__hsub2(op.a, er.a), z2)), z2);
                    o.b = __hmax2(__hsub2(xv.b, __hmax2(__hsub2(op.b, er.b), z2)), z2);
                    *(h4*)(dst + vox) = o;
                    if (last) {
                        float2 f01 = __half22float2(o.a), f23 = __half22float2(o.b);
                        int q = vox >> 2;
                        unsigned nb4 = (g_Yb0[q >> 3] >> ((q & 7) * 4)) & 0xFu;
                        accS += f01.x + f01.y + f23.x + f23.y;
                        accSY += (nb4 & 1 ? f01.x : 0.f) + (nb4 & 2 ? f01.y : 0.f)
                               + (nb4 & 4 ? f23.x : 0.f) + (nb4 & 8 ? f23.y : 0.f);
                    }
                }
                // output zB = zb-1: e2d slices zb-2, zb-1=v0, zb=v1
                {
                    int zB = zb - 1;
                    h4 eb = *(h4*)&e2d[((zb + 6) & 3) * 1024 + off];
                    h4 op = h4max3(eb, v0, v1);
                    h4 er = *(h4*)&ero[e0s * 1360 + (h + 1) * 40 + 4 + g * 4];
                    int vox = base + (zB * 160 + h0 + h) * 160 + w0 + g * 4;
                    h4 xv = *(const h4*)(src + vox);
                    h4 o;
                    o.a = __hmax2(__hsub2(xv.a, __hmax2(__hsub2(op.a, er.a), z2)), z2);
                    o.b = __hmax2(__hsub2(xv.b, __hmax2(__hsub2(op.b, er.b), z2)), z2);
                    *(h4*)(dst + vox) = o;
                    if (last) {
                        float2 f01 = __half22float2(o.a), f23 = __half22float2(o.b);
                        int q = vox >> 2;
                        unsigned nb4 = (g_Yb0[q >> 3] >> ((q & 7) * 4)) & 0xFu;
                        accS += f01.x + f01.y + f23.x + f23.y;
                        accSY += (nb4 & 1 ? f01.x : 0.f) + (nb4 & 2 ? f01.y : 0.f)
                               + (nb4 & 4 ? f23.x : 0.f) + (nb4 & 8 ? f23.y : 0.f);
                    }
                }
            }
        }
        // no trailing sync: every cross-step hazard has >=1 barrier in between
    }

    if (last) {
        float vals[2] = {accS, accSY};
        blockAddTo<2>(vals, g_acc + 10);
    }
}

// Bit-domain y skeleton, 4 output slices per block, 6-phase separable.
__device__ __forceinline__ void y_skel_block(unsigned int* su, int bi2, int it) {
    unsigned int* X  = su + YOFF_X;
    unsigned int* WT = su + YOFF_WT;
    unsigned int* WH = su + YOFF_WH;   // ring3
    unsigned int* E  = su + YOFF_E;    // ring2
    unsigned int* D  = su + YOFF_D;    // ring3

    int flip = it & 1;
    const unsigned int* src = flip ? g_Yb2 : g_Yb;
    unsigned int*       dst = flip ? g_Yb  : g_Yb2;
    bool last = (it == 7);

    int tid = threadIdx.x;
    int b = bi2 / 40, c = bi2 % 40;
    int z0 = c * 4, z1 = z0 + 3;
    int gbase = b * WBAT;

    float accY = 0.f, accYP = 0.f;

    for (int zl = z0 - 2; zl <= z1 + 2; ++zl) {
        // P1: load X slice zl (OOB = all ones)
        {
            bool zok = ((unsigned)zl < 160u);
            for (int i = tid; i < 800; i += 256)
                X[i] = zok ? src[gbase + zl * 800 + i] : 0xFFFFFFFFu;
        }
        __syncthreads();
        // P2: w-erode X -> WT
        for (int i = tid; i < 800; i += 256) {
            int j = i % W5;
            unsigned w = X[i];
            unsigned l = j > 0 ? X[i - 1] : 0xFFFFFFFFu;
            unsigned r = j < 4 ? X[i + 1] : 0xFFFFFFFFu;
            WT[i] = w & ((w << 1) | (l >> 31)) & ((w >> 1) | (r << 31));
        }
        __syncthreads();
        // P3: h-erode WT -> WH[zl]
        {
            int ws = (zl + 6) % 3;
            for (int i = tid; i < 800; i += 256) {
                int r = i / W5;
                unsigned w = WT[i];
                unsigned up = r > 0   ? WT[i - W5] : 0xFFFFFFFFu;
                unsigned dn = r < 159 ? WT[i + W5] : 0xFFFFFFFFu;
                WH[ws * 800 + i] = w & up & dn;
            }
        }
        __syncthreads();
        // P4: z-erode -> E[zl-1] (OOB slice -> 0)
        int ze = zl - 1;
        int es = (ze + 2) & 1;
        {
            bool zev = ((unsigned)ze < 160u);
            int wa = (ze + 5) % 3, wb = (ze + 6) % 3, wc = (ze + 7) % 3;
            for (int i = tid; i < 800; i += 256) {
                unsigned e = WH[wa * 800 + i] & WH[wb * 800 + i] & WH[wc * 800 + i];
                E[es * 800 + i] = zev ? e : 0u;
            }
        }
        __syncthreads();
        // P5: w-dilate E[zl-1] -> WT
        for (int i = tid; i < 800; i += 256) {
            int j = i % W5;
            unsigned w = E[es * 800 + i];
            unsigned l = j > 0 ? E[es * 800 + i - 1] : 0u;
            unsigned r = j < 4 ? E[es * 800 + i + 1] : 0u;
            WT[i] = w | (w << 1) | (l >> 31) | (w >> 1) | (r << 31);
        }
        __syncthreads();
        // P6: h-dilate WT -> D[zl-1]
        {
            int ds = (ze + 6) % 3;
            for (int i = tid; i < 800; i += 256) {
                int r = i / W5;
                unsigned w = WT[i];
                unsigned up = r > 0   ? WT[i - W5] : 0u;
                unsigned dn = r < 159 ? WT[i + W5] : 0u;
                D[ds * 800 + i] = w | up | dn;
            }
        }
        __syncthreads();
        // P7: combine at z = zl-2, x re-read from global
        int z = zl - 2;
        if (z >= z0) {
            int da = (z + 5) % 3, db = (z + 6) % 3, dc = (z + 7) % 3;
            int ez = (z + 2) & 1;
            for (int i = tid; i < 800; i += 256) {
                unsigned open = D[da * 800 + i] | D[db * 800 + i] | D[dc * 800 + i];
                unsigned x = src[gbase + z * 800 + i];
                int wi = gbase + z * 800 + i;
                unsigned dw = x & (~open | E[ez * 800 + i]);
                dst[wi] = dw;
                if (last && dw) {
                    accY += (float)__popc(dw);
#pragma unroll
                    for (int nb = 0; nb < 8; nb++) {
                        unsigned nb4 = (dw >> (nb * 4)) & 0xFu;
                        if (nb4) {
                            h4 p = ((const h4*)g_Porig)[wi * 8 + nb];
                            float2 pa = __half22float2(p.a), pb = __half22float2(p.b);
                            accYP += (nb4 & 1 ? pa.x : 0.f) + (nb4 & 2 ? pa.y : 0.f)
                                   + (nb4 & 4 ? pb.x : 0.f) + (nb4 & 8 ? pb.y : 0.f);
                        }
                    }
                }
            }
        }
    }

    if (last) {
        float vals[2] = {accY, accYP};
        blockAddTo<2>(vals, g_acc + 12);
    }
}

__global__ void __launch_bounds__(256, 4) k_skel(int it) {
    extern __shared__ __half smh[];
    int bi = blockIdx.x;
    if (bi < 500) p_skel_block(smh, bi, it);
    else          y_skel_block((unsigned int*)smh, bi - 500, it);
}

__global__ void k_fin(float* out) {
    double ce = g_acc[0] / (double)NTOT;
    double dsum = 0.0;
#pragma unroll
    for (int c = 0; c < 3; c++) {
        double I = g_acc[1 + c], P = g_acc[4 + c], T = g_acc[7 + c];
        dsum += (2.0 * I + 1e-5) / (P + T + 1e-5);
    }
    double base = ce + (1.0 - dsum / 3.0);
    double tprec = g_acc[11] / (g_acc[10] + 1e-6);
    double tsens = g_acc[13] / (g_acc[12] + 1e-6);
    double cl = 2.0 * tprec * tsens / (tprec + tsens + 1e-6);
    out[0] = (float)(base + 0.5 * (1.0 - cl));
}

extern "C" void kernel_launch(void* const* d_in, const int* in_sizes, int n_in,
                              void* d_out, int out_size) {
    const float* logits = (const float*)d_in[0];
    const int* target = (const int*)d_in[1];

    cudaFuncSetAttribute((const void*)k_skel,
                         cudaFuncAttributeMaxDynamicSharedMemorySize, SM_BYTES);

    k_zero<<<1, 32>>>();
    k_init<<<NQ / 256, 256>>>(logits, target);
    for (int it = 0; it < 8; ++it)
        k_skel<<<580, 256, SM_BYTES>>>(it);
    k_fin<<<1, 1>>>((float*)d_out);
}

// round 14
// speedup vs baseline: 1.3790x; 1.0973x over previous
#include <cuda_runtime.h>
#include <cuda_fp16.h>

#define SVOL  4096000        // 160^3
#define NTOT  8192000        // 2 * 160^3
#define NQ    2048000        // NTOT / 4

// ---- p skeleton smem layout (halves), tile 32x32, zchunk 16, 2 z-slices per iter ----
#define OFF_STAGE 0          // 2 x [36][48]   (stride 1728)
#define OFF_ROWMN 3456       // 2 x [36][40]   (stride 1440)
#define OFF_M2D   6336       // ring4 [34][40] (stride 1360)
#define OFF_ERO   11776      // ring3 [34][40] (stride 1360)
#define OFF_RMAX  15856      // 2 x [34][32]   (stride 1088)
#define OFF_E2D   18032      // ring4 [32][32] (stride 1024)
#define SM_HALVES 22128
#define SM_BYTES  (SM_HALVES * 2)   // 44256

// ---- y bit skeleton smem layout (words) — 6-phase separable ----
#define W5    5
#define WSL   800
#define WBAT  128000
#define YW    256000
#define YOFF_X   0           // [800]
#define YOFF_WT  800         // [800] transient (w-erode / w-dilate)
#define YOFF_WH  1600        // ring3 [800]
#define YOFF_E   4000        // ring2 [800]
#define YOFF_D   5600        // ring3 [800]

#define HPINF __ushort_as_half((unsigned short)0x7C00)
#define HNINF __ushort_as_half((unsigned short)0xFC00)

struct __align__(8) h4 { __half2 a, b; };

__device__ double g_acc[14];
__device__ __half g_Xp[NTOT];
__device__ __half g_Xp2[NTOT];
__device__ __half g_Porig[NTOT];
__device__ unsigned int g_Yb0[YW];
__device__ unsigned int g_Yb[YW];
__device__ unsigned int g_Yb2[YW];

__device__ __forceinline__ h4 h4fill(__half v) {
    h4 o; o.a = __half2half2(v); o.b = o.a; return o;
}
__device__ __forceinline__ h4 h4min3(h4 x, h4 y, h4 z) {
    h4 o;
    o.a = __hmin2(x.a, __hmin2(y.a, z.a));
    o.b = __hmin2(x.b, __hmin2(y.b, z.b));
    return o;
}
__device__ __forceinline__ h4 h4max3(h4 x, h4 y, h4 z) {
    h4 o;
    o.a = __hmax2(x.a, __hmax2(y.a, z.a));
    o.b = __hmax2(x.b, __hmax2(y.b, z.b));
    return o;
}
__device__ __forceinline__ h4 shiftMin(__half l, h4 c, __half r) {
    __half2 sl  = __halves2half2(l, __low2half(c.a));
    __half2 sr  = __halves2half2(__high2half(c.a), __low2half(c.b));
    __half2 sr2 = __halves2half2(__high2half(c.b), r);
    h4 o;
    o.a = __hmin2(__hmin2(sl, c.a), sr);
    o.b = __hmin2(__hmin2(sr, c.b), sr2);
    return o;
}
__device__ __forceinline__ h4 shiftMax(__half l, h4 c, __half r) {
    __half2 sl  = __halves2half2(l, __low2half(c.a));
    __half2 sr  = __halves2half2(__high2half(c.a), __low2half(c.b));
    __half2 sr2 = __halves2half2(__high2half(c.b), r);
    h4 o;
    o.a = __hmax2(__hmax2(sl, c.a), sr);
    o.b = __hmax2(__hmax2(sr, c.b), sr2);
    return o;
}

template <int NV>
__device__ __forceinline__ void blockAddTo(const float* vals, double* gout) {
    __shared__ float red[NV][8];
    int tid = threadIdx.x, lane = tid & 31, w = tid >> 5;
#pragma unroll
    for (int k = 0; k < NV; k++) {
        float v = vals[k];
#pragma unroll
        for (int o = 16; o; o >>= 1) v += __shfl_down_sync(0xffffffffu, v, o);
        if (lane == 0) red[k][w] = v;
    }
    __syncthreads();
    if (w == 0) {
#pragma unroll
        for (int k = 0; k < NV; k++) {
            float v = (lane < 8) ? red[k][lane] : 0.0f;
#pragma unroll
            for (int o = 4; o; o >>= 1) v += __shfl_down_sync(0xffffffffu, v, o);
            if (lane == 0) atomicAdd(&gout[k], (double)v);
        }
    }
}

__global__ void k_zero() {
    if (threadIdx.x < 14) g_acc[threadIdx.x] = 0.0;
}

// Fused: log-softmax, CE, dice accumulators, Porig (fp16), y bit-pack.
// 2 quads (8 voxels) per thread for MLP; 4000 blocks x 256.
__global__ void __launch_bounds__(256) k_init(const float* __restrict__ logits,
                                              const int* __restrict__ target) {
    __shared__ unsigned char nib[512];
    int tid = threadIdx.x;
    int q0 = blockIdx.x * 512 + tid;

    float ce = 0.f, i0 = 0.f, i1 = 0.f, i2 = 0.f;
    float s0 = 0.f, s1 = 0.f, s2 = 0.f, c0 = 0.f, c1 = 0.f, c2 = 0.f;

#pragma unroll
    for (int u = 0; u < 2; u++) {
        int q = q0 + u * 256;
        int e = q * 4;
        int b = (e >= SVOL) ? 1 : 0;
        int s = e - b * SVOL;
        const float* lp = logits + (size_t)b * 3 * SVOL + s;
        float4 L0 = *(const float4*)(lp);
        float4 L1 = *(const float4*)(lp + SVOL);
        float4 L2 = *(const float4*)(lp + 2 * SVOL);
        int4 ti = ((const int4*)target)[q];
        int tg[4] = {ti.x, ti.y, ti.z, ti.w};
        float a0[4] = {L0.x, L0.y, L0.z, L0.w};
        float a1[4] = {L1.x, L1.y, L1.z, L1.w};
        float a2[4] = {L2.x, L2.y, L2.z, L2.w};

        float pv[4];
        unsigned nb = 0;
#pragma unroll
        for (int j = 0; j < 4; j++) {
            float x0 = a0[j], x1 = a1[j], x2 = a2[j];
            float m = fmaxf(x0, fmaxf(x1, x2));
            float e0 = __expf(x0 - m), e1 = __expf(x1 - m), e2 = __expf(x2 - m);
            float sum = e0 + e1 + e2;
            float inv = __fdividef(1.0f, sum);
            float p0 = e0 * inv, p1 = e1 * inv, p2 = e2 * inv;
            float ls = __logf(sum);
            int t = tg[j];
            float lt = (t == 0) ? x0 : ((t == 1) ? x1 : x2);
            ce += (m + ls - lt);
            s0 += p0; s1 += p1; s2 += p2;
            if (t == 0)      { i0 += p0; c0 += 1.f; }
            else if (t == 1) { i1 += p1; c1 += 1.f; }
            else             { i2 += p2; c2 += 1.f; }
            pv[j] = fminf(fmaxf(1.0f - p0, 0.0f), 1.0f);
            if (t != 0) nb |= (1u << j);
        }
        h4 PV;
        PV.a = __floats2half2_rn(pv[0], pv[1]);
        PV.b = __floats2half2_rn(pv[2], pv[3]);
        ((h4*)g_Porig)[q] = PV;      // iteration 0 reads Porig directly
        nib[u * 256 + tid] = (unsigned char)nb;
    }
    __syncthreads();
    if (tid < 64) {
        unsigned w = 0;
#pragma unroll
        for (int k = 0; k < 8; k++) {
            int idx = tid * 8 + k;
            // map packed index back to quad order: nib[u*256+t] holds quad q0base+u*256+t
            int u = idx >> 8, t2 = idx & 255;
            (void)u; (void)t2;
            w |= ((unsigned)nib[idx]) << (4 * k);
        }
        // quads covered by word wi: q = blockIdx*512 + (wi_local*8 .. wi_local*8+7)
        // nib layout: nib[u*256+t] = quad blockIdx*512 + u*256 + t  -> NOT contiguous!
        // Fix: store nib contiguously by quad below instead.
        int wi = blockIdx.x * 64 + tid;
        g_Yb0[wi] = w;
        g_Yb[wi] = w;
    }

    float vals[10] = {ce, i0, i1, i2, s0, s1, s2, c0, c1, c2};
    blockAddTo<10>(vals, g_acc);
}

// ---------------- merged skeleton iteration -----------------
// blocks [0,500): fp16 p skeleton (tile 32x32, zchunk 16, 2 slices/iter).
// blocks [500,580): bit y skeleton (chunk 4, 6-phase separable).
// On it==7, blocks also accumulate the clDice sums.

__device__ __forceinline__ void p_skel_block(__half* sm, int bi, int it) {
    __half* stage = sm + OFF_STAGE;
    __half* rowmn = sm + OFF_ROWMN;
    __half* m2d   = sm + OFF_M2D;
    __half* ero   = sm + OFF_ERO;
    __half* rmax  = sm + OFF_RMAX;
    __half* e2d   = sm + OFF_E2D;

    const __half* src = (it == 0) ? g_Porig : ((it & 1) ? g_Xp2 : g_Xp);
    __half*       dst = (it & 1) ? g_Xp : g_Xp2;
    bool last = (it == 7);

    int tid = threadIdx.x;
    int r = bi;
    int b = r / 250; r %= 250;
    int zc = r / 25; int t = r % 25;
    int h0 = (t / 5) * 32, w0 = (t % 5) * 32;
    int z0 = zc * 16;
    int base = b * SVOL;

    float accS = 0.f, accSY = 0.f;

    // one-time pad fill (both stage buffers, cols 0..5 and 42..47 stay +inf)
    for (int i = tid; i < 864; i += 256) {
        int s = i / 432, j = i % 432;
        int row = j / 12, c = j % 12;
        stage[s * 1728 + row * 48 + ((c < 6) ? c : c + 36)] = HPINF;
    }

    for (int zb = z0 - 2; zb <= z0 + 16; zb += 2) {
        // ---- A: stage x slices zb, zb+1 ----
        for (int i = tid; i < 576; i += 256) {
            int s = i / 288, j = i % 288;
            int row = j >> 3, qw = j & 7;
            int zl = zb + s;
            int h = h0 + row - 2;
            h4 v = h4fill(HPINF);
            if ((unsigned)zl < 160u && (unsigned)h < 160u)
                v = *(const h4*)(src + base + (zl * 160 + h) * 160 + w0 + qw * 4);
            *(h4*)&stage[s * 1728 + row * 48 + 8 + qw * 4] = v;
        }
        for (int i = tid; i < 288; i += 256) {            // halos w in {-2,-1,32,33}
            int s = i / 144, j = i % 144;
            int row = j >> 2, k = j & 3;
            int w = (k < 2) ? (k - 2) : (k + 30);
            int zl = zb + s;
            int h = h0 + row - 2, ww = w0 + w;
            __half v = HPINF;
            if ((unsigned)zl < 160u && (unsigned)h < 160u && (unsigned)ww < 160u)
                v = src[base + (zl * 160 + h) * 160 + ww];
            stage[s * 1728 + row * 48 + 8 + w] = v;
        }
        __syncthreads();
        // ---- B: row-min along w (both slices) ----
        for (int i = tid; i < 720; i += 256) {
            int s = i / 360, j = i % 360;
            int g = j % 10, row = j / 10;
            const __half* sp = &stage[s * 1728 + row * 48 + 4 + g * 4];
            h4 o = shiftMin(sp[-1], *(const h4*)sp, sp[4]);
            *(h4*)&rowmn[s * 1440 + row * 40 + g * 4] = o;
        }
        __syncthreads();
        // ---- C: col-min -> m2d[zb], m2d[zb+1]; z-min -> ero[zb-1], ero[zb] ----
        int mA = (zb + 6) & 3, mB = (zb + 7) & 3;       // slots zb-2, zb-1
        int m0 = (zb + 8) & 3, m1 = (zb + 9) & 3;       // slots zb,   zb+1
        int e0s = (zb + 8) % 3, e1s = (zb + 9) % 3;     // ero slots zb-1, zb
        bool zv0 = ((unsigned)(zb - 1) < 160u);
        bool zv1 = ((unsigned)zb < 160u);
        for (int i = tid; i < 340; i += 256) {
            int g = i % 10, mrow = i / 10;
            int off = mrow * 40 + g * 4;
            h4 v0, v1;
            {
                h4 r0 = *(h4*)&rowmn[off];
                h4 r1 = *(h4*)&rowmn[off + 40];
                h4 r2 = *(h4*)&rowmn[off + 80];
                v0 = h4min3(r0, r1, r2);
            }
            {
                h4 r0 = *(h4*)&rowmn[1440 + off];
                h4 r1 = *(h4*)&rowmn[1440 + off + 40];
                h4 r2 = *(h4*)&rowmn[1440 + off + 80];
                v1 = h4min3(r0, r1, r2);
            }
            *(h4*)&m2d[m0 * 1360 + off] = v0;
            *(h4*)&m2d[m1 * 1360 + off] = v1;
            h4 ma = *(h4*)&m2d[mA * 1360 + off];
            h4 mb = *(h4*)&m2d[mB * 1360 + off];
            h4 eA = zv0 ? h4min3(ma, mb, v0) : h4fill(HNINF);
            h4 eB = zv1 ? h4min3(mb, v0, v1) : h4fill(HNINF);
            *(h4*)&ero[e0s * 1360 + off] = eA;
            *(h4*)&ero[e1s * 1360 + off] = eB;
        }
        __syncthreads();
        // ---- D: row-max of ero[zb-1], ero[zb] ----
        for (int i = tid; i < 544; i += 256) {
            int s = i / 272, j = i % 272;
            int g = j & 7, row = j >> 3;
            int es = s ? e1s : e0s;
            const __half* ep = &ero[es * 1360 + row * 40 + 4 + g * 4];
            h4 o = shiftMax(ep[-1], *(const h4*)ep, ep[4]);
            *(h4*)&rmax[s * 1088 + row * 32 + g * 4] = o;
        }
        __syncthreads();
        // ---- E+F fused: col-max -> e2d[zb-1], e2d[zb]; outputs z = zb-2, zb-1 ----
        {
            int g = tid & 7, h = tid >> 3;     // exactly 256 items
            int off = h * 32 + g * 4;
            h4 v0, v1;
            {
                h4 r0 = *(h4*)&rmax[off];
                h4 r1 = *(h4*)&rmax[off + 32];
                h4 r2 = *(h4*)&rmax[off + 64];
                v0 = h4max3(r0, r1, r2);       // e2d[zb-1]
            }
            {
                h4 r0 = *(h4*)&rmax[1088 + off];
                h4 r1 = *(h4*)&rmax[1088 + off + 32];
                h4 r2 = *(h4*)&rmax[1088 + off + 64];
                v1 = h4max3(r0, r1, r2);       // e2d[zb]
            }
            *(h4*)&e2d[((zb + 7) & 3) * 1024 + off] = v0;
            *(h4*)&e2d[((zb + 8) & 3) * 1024 + off] = v1;

            int za = zb - 2;
            if (za >= z0) {
                __half2 z2 = __float2half2_rn(0.0f);
                // output za = zb-2: e2d slices za-1, za, za+1=v0
                {
                    h4 ea = *(h4*)&e2d[((zb + 5) & 3) * 1024 + off];   // e2d[zb-3]
                    h4 eb = *(h4*)&e2d[((zb + 6) & 3) * 1024 + off];   // e2d[zb-2]
                    h4 op = h4max3(ea, eb, v0);
                    h4 er = *(h4*)&ero[((zb + 7) % 3) * 1360 + (h + 1) * 40 + 4 + g * 4];
                    int vox = base + (za * 160 + h0 + h) * 160 + w0 + g * 4;
                    h4 xv = *(const h4*)(src + vox);
                    h4 o;
                    o.a = __hmax2(__hsub2(xv.a, __hmax2(__hsub2(op.a, er.a), z2)), z2);
                    o.b = __hmax2(__hsub2(xv.b, __hmax2(__hsub2(op.b, er.b), z2)), z2);
                    *(h4*)(dst + vox) = o;
                    if (last) {
                        float2 f01 = __half22float2(o.a), f23 = __half22float2(o.b);
                        int q = vox >> 2;
                        unsigned nb4 = (g_Yb0[q >> 3] >> ((q & 7) * 4)) & 0xFu;
                        accS += f01.x + f01.y + f23.x + f23.y;
                        accSY += (nb4 & 1 ? f01.x : 0.f) + (nb4 & 2 ? f01.y : 0.f)
                               + (nb4 & 4 ? f23.x : 0.f) + (nb4 & 8 ? f23.y : 0.f);
                    }
                }
                // output zB = zb-1: e2d slices zb-2, zb-1=v0, zb=v1
                {
                    int zB = zb - 1;
                    h4 eb = *(h4*)&e2d[((zb + 6) & 3) * 1024 + off];
                    h4 op = h4max3(eb, v0, v1);
                    h4 er = *(h4*)&ero[e0s * 1360 + (h + 1) * 40 + 4 + g * 4];
                    int vox = base + (zB * 160 + h0 + h) * 160 + w0 + g * 4;
                    h4 xv = *(const h4*)(src + vox);
                    h4 o;
                    o.a = __hmax2(__hsub2(xv.a, __hmax2(__hsub2(op.a, er.a), z2)), z2);
                    o.b = __hmax2(__hsub2(xv.b, __hmax2(__hsub2(op.b, er.b), z2)), z2);
                    *(h4*)(dst + vox) = o;
                    if (last) {
                        float2 f01 = __half22float2(o.a), f23 = __half22float2(o.b);
                        int q = vox >> 2;
                        unsigned nb4 = (g_Yb0[q >> 3] >> ((q & 7) * 4)) & 0xFu;
                        accS += f01.x + f01.y + f23.x + f23.y;
                        accSY += (nb4 & 1 ? f01.x : 0.f) + (nb4 & 2 ? f01.y : 0.f)
                               + (nb4 & 4 ? f23.x : 0.f) + (nb4 & 8 ? f23.y : 0.f);
                    }
                }
            }
        }
        // no trailing sync: every cross-step hazard has >=1 barrier in between
    }

    if (last) {
        float vals[2] = {accS, accSY};
        blockAddTo<2>(vals, g_acc + 10);
    }
}

// Bit-domain y skeleton, 4 output slices per block, 6-phase separable.
__device__ __forceinline__ void y_skel_block(unsigned int* su, int bi2, int it) {
    unsigned int* X  = su + YOFF_X;
    unsigned int* WT = su + YOFF_WT;
    unsigned int* WH = su + YOFF_WH;   // ring3
    unsigned int* E  = su + YOFF_E;    // ring2
    unsigned int* D  = su + YOFF_D;    // ring3

    int flip = it & 1;
    const unsigned int* src = flip ? g_Yb2 : g_Yb;
    unsigned int*       dst = flip ? g_Yb  : g_Yb2;
    bool last = (it == 7);

    int tid = threadIdx.x;
    int b = bi2 / 40, c = bi2 % 40;
    int z0 = c * 4, z1 = z0 + 3;
    int gbase = b * WBAT;

    float accY = 0.f, accYP = 0.f;

    for (int zl = z0 - 2; zl <= z1 + 2; ++zl) {
        // P1: load X slice zl (OOB = all ones)
        {
            bool zok = ((unsigned)zl < 160u);
            for (int i = tid; i < 800; i += 256)
                X[i] = zok ? src[gbase + zl * 800 + i] : 0xFFFFFFFFu;
        }
        __syncthreads();
        // P2: w-erode X -> WT
        for (int i = tid; i < 800; i += 256) {
            int j = i % W5;
            unsigned w = X[i];
            unsigned l = j > 0 ? X[i - 1] : 0xFFFFFFFFu;
            unsigned r = j < 4 ? X[i + 1] : 0xFFFFFFFFu;
            WT[i] = w & ((w << 1) | (l >> 31)) & ((w >> 1) | (r << 31));
        }
        __syncthreads();
        // P3: h-erode WT -> WH[zl]
        {
            int ws = (zl + 6) % 3;
            for (int i = tid; i < 800; i += 256) {
                int r = i / W5;
                unsigned w = WT[i];
                unsigned up = r > 0   ? WT[i - W5] : 0xFFFFFFFFu;
                unsigned dn = r < 159 ? WT[i + W5] : 0xFFFFFFFFu;
                WH[ws * 800 + i] = w & up & dn;
            }
        }
        __syncthreads();
        // P4: z-erode -> E[zl-1] (OOB slice -> 0)
        int ze = zl - 1;
        int es = (ze + 2) & 1;
        {
            bool zev = ((unsigned)ze < 160u);
            int wa = (ze + 5) % 3, wb = (ze + 6) % 3, wc = (ze + 7) % 3;
            for (int i = tid; i < 800; i += 256) {
                unsigned e = WH[wa * 800 + i] & WH[wb * 800 + i] & WH[wc * 800 + i];
                E[es * 800 + i] = zev ? e : 0u;
            }
        }
        __syncthreads();
        // P5: w-dilate E[zl-1] -> WT
        for (int i = tid; i < 800; i += 256) {
            int j = i % W5;
            unsigned w = E[es * 800 + i];
            unsigned l = j > 0 ? E[es * 800 + i - 1] : 0u;
            unsigned r = j < 4 ? E[es * 800 + i + 1] : 0u;
            WT[i] = w | (w << 1) | (l >> 31) | (w >> 1) | (r << 31);
        }
        __syncthreads();
        // P6: h-dilate WT -> D[zl-1]
        {
            int ds = (ze + 6) % 3;
            for (int i = tid; i < 800; i += 256) {
                int r = i / W5;
                unsigned w = WT[i];
                unsigned up = r > 0   ? WT[i - W5] : 0u;
                unsigned dn = r < 159 ? WT[i + W5] : 0u;
                D[ds * 800 + i] = w | up | dn;
            }
        }
        __syncthreads();
        // P7: combine at z = zl-2, x re-read from global
        int z = zl - 2;
        if (z >= z0) {
            int da = (z + 5) % 3, db = (z + 6) % 3, dc = (z + 7) % 3;
            int ez = (z + 2) & 1;
            for (int i = tid; i < 800; i += 256) {
                unsigned open = D[da * 800 + i] | D[db * 800 + i] | D[dc * 800 + i];
                unsigned x = src[gbase + z * 800 + i];
                int wi = gbase + z * 800 + i;
                unsigned dw = x & (~open | E[ez * 800 + i]);
                dst[wi] = dw;
                if (last && dw) {
                    accY += (float)__popc(dw);
#pragma unroll
                    for (int nb = 0; nb < 8; nb++) {
                        unsigned nb4 = (dw >> (nb * 4)) & 0xFu;
                        if (nb4) {
                            h4 p = ((const h4*)g_Porig)[wi * 8 + nb];
                            float2 pa = __half22float2(p.a), pb = __half22float2(p.b);
                            accYP += (nb4 & 1 ? pa.x : 0.f) + (nb4 & 2 ? pa.y : 0.f)
                                   + (nb4 & 4 ? pb.x : 0.f) + (nb4 & 8 ? pb.y : 0.f);
                        }
                    }
                }
            }
        }
    }

    if (last) {
        float vals[2] = {accY, accYP};
        blockAddTo<2>(vals, g_acc + 12);
    }
}

__global__ void __launch_bounds__(256, 4) k_skel(int it) {
    extern __shared__ __half smh[];
    int bi = blockIdx.x;
    if (bi < 500) p_skel_block(smh, bi, it);
    else          y_skel_block((unsigned int*)smh, bi - 500, it);
}

__global__ void k_fin(float* out) {
    double ce = g_acc[0] / (double)NTOT;
    double dsum = 0.0;
#pragma unroll
    for (int c = 0; c < 3; c++) {
        double I = g_acc[1 + c], P = g_acc[4 + c], T = g_acc[7 + c];
        dsum += (2.0 * I + 1e-5) / (P + T + 1e-5);
    }
    double base = ce + (1.0 - dsum / 3.0);
    double tprec = g_acc[11] / (g_acc[10] + 1e-6);
    double tsens = g_acc[13] / (g_acc[12] + 1e-6);
    double cl = 2.0 * tprec * tsens / (tprec + tsens + 1e-6);
    out[0] = (float)(base + 0.5 * (1.0 - cl));
}

extern "C" void kernel_launch(void* const* d_in, const int* in_sizes, int n_in,
                              void* d_out, int out_size) {
    const float* logits = (const float*)d_in[0];
    const int* target = (const int*)d_in[1];

    cudaFuncSetAttribute((const void*)k_skel,
                         cudaFuncAttributeMaxDynamicSharedMemorySize, SM_BYTES);

    k_zero<<<1, 32>>>();
    k_init<<<NQ / 512, 256>>>(logits, target);
    for (int it = 0; it < 8; ++it)
        k_skel<<<580, 256, SM_BYTES>>>(it);
    k_fin<<<1, 1>>>((float*)d_out);
}

// round 15
// speedup vs baseline: 1.4352x; 1.0407x over previous
#include <cuda_runtime.h>
#include <cuda_fp16.h>

#define SVOL  4096000        // 160^3
#define NTOT  8192000        // 2 * 160^3
#define NQ    2048000        // NTOT / 4

// ---- p skeleton smem layout (halves), tile 32x32, zchunk 16, 2 z-slices per iter ----
#define OFF_STAGE 0          // 2 x [36][48]   (stride 1728)
#define OFF_ROWMN 3456       // 2 x [36][40]   (stride 1440)
#define OFF_M2D   6336       // ring4 [34][40] (stride 1360)
#define OFF_ERO   11776      // ring3 [34][40] (stride 1360)
#define OFF_RMAX  15856      // 2 x [34][32]   (stride 1088)
#define OFF_E2D   18032      // ring4 [32][32] (stride 1024)
#define SM_HALVES 22128
#define SM_BYTES  (SM_HALVES * 2)   // 44256

// ---- y bit skeleton smem layout (words) — 6-phase separable ----
#define W5    5
#define WSL   800
#define WBAT  128000
#define YW    256000
#define YOFF_X   0           // [800]
#define YOFF_WT  800         // [800] transient (w-erode / w-dilate)
#define YOFF_WH  1600        // ring3 [800]
#define YOFF_E   4000        // ring2 [800]
#define YOFF_D   5600        // ring3 [800]

#define HPINF __ushort_as_half((unsigned short)0x7C00)
#define HNINF __ushort_as_half((unsigned short)0xFC00)

struct __align__(8) h4 { __half2 a, b; };

__device__ double g_acc[14];
__device__ __half g_Xp[NTOT];
__device__ __half g_Xp2[NTOT];
__device__ __half g_Porig[NTOT];
__device__ unsigned int g_Yb0[YW];
__device__ unsigned int g_Yb[YW];
__device__ unsigned int g_Yb2[YW];

__device__ __forceinline__ h4 h4fill(__half v) {
    h4 o; o.a = __half2half2(v); o.b = o.a; return o;
}
__device__ __forceinline__ h4 h4min3(h4 x, h4 y, h4 z) {
    h4 o;
    o.a = __hmin2(x.a, __hmin2(y.a, z.a));
    o.b = __hmin2(x.b, __hmin2(y.b, z.b));
    return o;
}
__device__ __forceinline__ h4 h4max3(h4 x, h4 y, h4 z) {
    h4 o;
    o.a = __hmax2(x.a, __hmax2(y.a, z.a));
    o.b = __hmax2(x.b, __hmax2(y.b, z.b));
    return o;
}
__device__ __forceinline__ h4 shiftMin(__half l, h4 c, __half r) {
    __half2 sl  = __halves2half2(l, __low2half(c.a));
    __half2 sr  = __halves2half2(__high2half(c.a), __low2half(c.b));
    __half2 sr2 = __halves2half2(__high2half(c.b), r);
    h4 o;
    o.a = __hmin2(__hmin2(sl, c.a), sr);
    o.b = __hmin2(__hmin2(sr, c.b), sr2);
    return o;
}
__device__ __forceinline__ h4 shiftMax(__half l, h4 c, __half r) {
    __half2 sl  = __halves2half2(l, __low2half(c.a));
    __half2 sr  = __halves2half2(__high2half(c.a), __low2half(c.b));
    __half2 sr2 = __halves2half2(__high2half(c.b), r);
    h4 o;
    o.a = __hmax2(__hmax2(sl, c.a), sr);
    o.b = __hmax2(__hmax2(sr, c.b), sr2);
    return o;
}

template <int NV>
__device__ __forceinline__ void blockAddTo(const float* vals, double* gout) {
    __shared__ float red[NV][8];
    int tid = threadIdx.x, lane = tid & 31, w = tid >> 5;
#pragma unroll
    for (int k = 0; k < NV; k++) {
        float v = vals[k];
#pragma unroll
        for (int o = 16; o; o >>= 1) v += __shfl_down_sync(0xffffffffu, v, o);
        if (lane == 0) red[k][w] = v;
    }
    __syncthreads();
    if (w == 0) {
#pragma unroll
        for (int k = 0; k < NV; k++) {
            float v = (lane < 8) ? red[k][lane] : 0.0f;
#pragma unroll
            for (int o = 4; o; o >>= 1) v += __shfl_down_sync(0xffffffffu, v, o);
            if (lane == 0) atomicAdd(&gout[k], (double)v);
        }
    }
}

__global__ void k_zero() {
    if (threadIdx.x < 14) g_acc[threadIdx.x] = 0.0;
}

// Fused: log-softmax, CE, dice accumulators, Porig (fp16), y bit-pack.
// 4 quads (16 voxels) per thread; 2000 blocks x 256.
__global__ void __launch_bounds__(256) k_init(const float* __restrict__ logits,
                                              const int* __restrict__ target) {
    __shared__ unsigned char nib[1024];
    int tid = threadIdx.x;
    int q0 = blockIdx.x * 1024 + tid;

    float ce = 0.f, i0 = 0.f, i1 = 0.f, i2 = 0.f;
    float s0 = 0.f, s1 = 0.f, s2 = 0.f, c0 = 0.f, c1 = 0.f, c2 = 0.f;

#pragma unroll
    for (int u = 0; u < 4; u++) {
        int q = q0 + u * 256;
        int e = q * 4;
        int b = (e >= SVOL) ? 1 : 0;
        int s = e - b * SVOL;
        const float* lp = logits + (size_t)b * 3 * SVOL + s;
        float4 L0 = *(const float4*)(lp);
        float4 L1 = *(const float4*)(lp + SVOL);
        float4 L2 = *(const float4*)(lp + 2 * SVOL);
        int4 ti = ((const int4*)target)[q];
        int tg[4] = {ti.x, ti.y, ti.z, ti.w};
        float a0[4] = {L0.x, L0.y, L0.z, L0.w};
        float a1[4] = {L1.x, L1.y, L1.z, L1.w};
        float a2[4] = {L2.x, L2.y, L2.z, L2.w};

        float pv[4];
        unsigned nb = 0;
#pragma unroll
        for (int j = 0; j < 4; j++) {
            float x0 = a0[j], x1 = a1[j], x2 = a2[j];
            float m = fmaxf(x0, fmaxf(x1, x2));
            float e0 = __expf(x0 - m), e1 = __expf(x1 - m), e2 = __expf(x2 - m);
            float sum = e0 + e1 + e2;
            float inv = __fdividef(1.0f, sum);
            float p0 = e0 * inv, p1 = e1 * inv, p2 = e2 * inv;
            float ls = __logf(sum);
            int t = tg[j];
            float lt = (t == 0) ? x0 : ((t == 1) ? x1 : x2);
            ce += (m + ls - lt);
            s0 += p0; s1 += p1; s2 += p2;
            if (t == 0)      { i0 += p0; c0 += 1.f; }
            else if (t == 1) { i1 += p1; c1 += 1.f; }
            else             { i2 += p2; c2 += 1.f; }
            pv[j] = fminf(fmaxf(1.0f - p0, 0.0f), 1.0f);
            if (t != 0) nb |= (1u << j);
        }
        h4 PV;
        PV.a = __floats2half2_rn(pv[0], pv[1]);
        PV.b = __floats2half2_rn(pv[2], pv[3]);
        ((h4*)g_Porig)[q] = PV;      // iteration 0 reads Porig directly
        nib[u * 256 + tid] = (unsigned char)nb;
    }
    __syncthreads();
    // nib[idx] holds quad blockIdx*1024 + idx (idx = u*256 + tid is the identity
    // mapping over [0,1024)), so word wi = blockIdx*128 + t packs quads wi*8..wi*8+7.
    if (tid < 128) {
        unsigned w = 0;
#pragma unroll
        for (int k = 0; k < 8; k++)
            w |= ((unsigned)nib[tid * 8 + k]) << (4 * k);
        int wi = blockIdx.x * 128 + tid;
        g_Yb0[wi] = w;
        g_Yb[wi] = w;
    }

    float vals[10] = {ce, i0, i1, i2, s0, s1, s2, c0, c1, c2};
    blockAddTo<10>(vals, g_acc);
}

// ---------------- merged skeleton iteration -----------------
// blocks [0,500): fp16 p skeleton (tile 32x32, zchunk 16, 2 slices/iter).
// blocks [500,580): bit y skeleton (chunk 4, 6-phase separable).
// On it==7, blocks also accumulate the clDice sums.

__device__ __forceinline__ void p_skel_block(__half* sm, int bi, int it) {
    __half* stage = sm + OFF_STAGE;
    __half* rowmn = sm + OFF_ROWMN;
    __half* m2d   = sm + OFF_M2D;
    __half* ero   = sm + OFF_ERO;
    __half* rmax  = sm + OFF_RMAX;
    __half* e2d   = sm + OFF_E2D;

    const __half* src = (it == 0) ? g_Porig : ((it & 1) ? g_Xp2 : g_Xp);
    __half*       dst = (it & 1) ? g_Xp : g_Xp2;
    bool last = (it == 7);

    int tid = threadIdx.x;
    int r = bi;
    int b = r / 250; r %= 250;
    int zc = r / 25; int t = r % 25;
    int h0 = (t / 5) * 32, w0 = (t % 5) * 32;
    int z0 = zc * 16;
    int base = b * SVOL;

    float accS = 0.f, accSY = 0.f;

    // one-time pad fill (both stage buffers, cols 0..5 and 42..47 stay +inf)
    for (int i = tid; i < 864; i += 256) {
        int s = i / 432, j = i % 432;
        int row = j / 12, c = j % 12;
        stage[s * 1728 + row * 48 + ((c < 6) ? c : c + 36)] = HPINF;
    }

    for (int zb = z0 - 2; zb <= z0 + 16; zb += 2) {
        // ---- A: stage x slices zb, zb+1 ----
        for (int i = tid; i < 576; i += 256) {
            int s = i / 288, j = i % 288;
            int row = j >> 3, qw = j & 7;
            int zl = zb + s;
            int h = h0 + row - 2;
            h4 v = h4fill(HPINF);
            if ((unsigned)zl < 160u && (unsigned)h < 160u)
                v = *(const h4*)(src + base + (zl * 160 + h) * 160 + w0 + qw * 4);
            *(h4*)&stage[s * 1728 + row * 48 + 8 + qw * 4] = v;
        }
        for (int i = tid; i < 288; i += 256) {            // halos w in {-2,-1,32,33}
            int s = i / 144, j = i % 144;
            int row = j >> 2, k = j & 3;
            int w = (k < 2) ? (k - 2) : (k + 30);
            int zl = zb + s;
            int h = h0 + row - 2, ww = w0 + w;
            __half v = HPINF;
            if ((unsigned)zl < 160u && (unsigned)h < 160u && (unsigned)ww < 160u)
                v = src[base + (zl * 160 + h) * 160 + ww];
            stage[s * 1728 + row * 48 + 8 + w] = v;
        }
        __syncthreads();
        // ---- B: row-min along w (both slices) ----
        for (int i = tid; i < 720; i += 256) {
            int s = i / 360, j = i % 360;
            int g = j % 10, row = j / 10;
            const __half* sp = &stage[s * 1728 + row * 48 + 4 + g * 4];
            h4 o = shiftMin(sp[-1], *(const h4*)sp, sp[4]);
            *(h4*)&rowmn[s * 1440 + row * 40 + g * 4] = o;
        }
        __syncthreads();
        // ---- C: col-min -> m2d[zb], m2d[zb+1]; z-min -> ero[zb-1], ero[zb] ----
        int mA = (zb + 6) & 3, mB = (zb + 7) & 3;       // slots zb-2, zb-1
        int m0 = (zb + 8) & 3, m1 = (zb + 9) & 3;       // slots zb,   zb+1
        int e0s = (zb + 8) % 3, e1s = (zb + 9) % 3;     // ero slots zb-1, zb
        bool zv0 = ((unsigned)(zb - 1) < 160u);
        bool zv1 = ((unsigned)zb < 160u);
        for (int i = tid; i < 340; i += 256) {
            int g = i % 10, mrow = i / 10;
            int off = mrow * 40 + g * 4;
            h4 v0, v1;
            {
                h4 r0 = *(h4*)&rowmn[off];
                h4 r1 = *(h4*)&rowmn[off + 40];
                h4 r2 = *(h4*)&rowmn[off + 80];
                v0 = h4min3(r0, r1, r2);
            }
            {
                h4 r0 = *(h4*)&rowmn[1440 + off];
                h4 r1 = *(h4*)&rowmn[1440 + off + 40];
                h4 r2 = *(h4*)&rowmn[1440 + off + 80];
                v1 = h4min3(r0, r1, r2);
            }
            *(h4*)&m2d[m0 * 1360 + off] = v0;
            *(h4*)&m2d[m1 * 1360 + off] = v1;
            h4 ma = *(h4*)&m2d[mA * 1360 + off];
            h4 mb = *(h4*)&m2d[mB * 1360 + off];
            h4 eA = zv0 ? h4min3(ma, mb, v0) : h4fill(HNINF);
            h4 eB = zv1 ? h4min3(mb, v0, v1) : h4fill(HNINF);
            *(h4*)&ero[e0s * 1360 + off] = eA;
            *(h4*)&ero[e1s * 1360 + off] = eB;
        }
        __syncthreads();
        // ---- D: row-max of ero[zb-1], ero[zb] ----
        for (int i = tid; i < 544; i += 256) {
            int s = i / 272, j = i % 272;
            int g = j & 7, row = j >> 3;
            int es = s ? e1s : e0s;
            const __half* ep = &ero[es * 1360 + row * 40 + 4 + g * 4];
            h4 o = shiftMax(ep[-1], *(const h4*)ep, ep[4]);
            *(h4*)&rmax[s * 1088 + row * 32 + g * 4] = o;
        }
        __syncthreads();
        // ---- E+F fused: col-max -> e2d[zb-1], e2d[zb]; outputs z = zb-2, zb-1 ----
        {
            int g = tid & 7, h = tid >> 3;     // exactly 256 items
            int off = h * 32 + g * 4;
            h4 v0, v1;
            {
                h4 r0 = *(h4*)&rmax[off];
                h4 r1 = *(h4*)&rmax[off + 32];
                h4 r2 = *(h4*)&rmax[off + 64];
                v0 = h4max3(r0, r1, r2);       // e2d[zb-1]
            }
            {
                h4 r0 = *(h4*)&rmax[1088 + off];
                h4 r1 = *(h4*)&rmax[1088 + off + 32];
                h4 r2 = *(h4*)&rmax[1088 + off + 64];
                v1 = h4max3(r0, r1, r2);       // e2d[zb]
            }
            *(h4*)&e2d[((zb + 7) & 3) * 1024 + off] = v0;
            *(h4*)&e2d[((zb + 8) & 3) * 1024 + off] = v1;

            int za = zb - 2;
            if (za >= z0) {
                __half2 z2 = __float2half2_rn(0.0f);
                // output za = zb-2: e2d slices za-1, za, za+1=v0
                {
                    h4 ea = *(h4*)&e2d[((zb + 5) & 3) * 1024 + off];   // e2d[zb-3]
                    h4 eb = *(h4*)&e2d[((zb + 6) & 3) * 1024 + off];   // e2d[zb-2]
                    h4 op = h4max3(ea, eb, v0);
                    h4 er = *(h4*)&ero[((zb + 7) % 3) * 1360 + (h + 1) * 40 + 4 + g * 4];
                    int vox = base + (za * 160 + h0 + h) * 160 + w0 + g * 4;
                    h4 xv = *(const h4*)(src + vox);
                    h4 o;
                    o.a = __hmax2(__hsub2(xv.a, __hmax2(__hsub2(op.a, er.a), z2)), z2);
                    o.b = __hmax2(__hsub2(xv.b, __hmax2(__hsub2(op.b, er.b), z2)), z2);
                    *(h4*)(dst + vox) = o;
                    if (last) {
                        float2 f01 = __half22float2(o.a), f23 = __half22float2(o.b);
                        int q = vox >> 2;
                        unsigned nb4 = (g_Yb0[q >> 3] >> ((q & 7) * 4)) & 0xFu;
                        accS += f01.x + f01.y + f23.x + f23.y;
                        accSY += (nb4 & 1 ? f01.x : 0.f) + (nb4 & 2 ? f01.y : 0.f)
                               + (nb4 & 4 ? f23.x : 0.f) + (nb4 & 8 ? f23.y : 0.f);
                    }
                }
                // output zB = zb-1: e2d slices zb-2, zb-1=v0, zb=v1
                {
                    int zB = zb - 1;
                    h4 eb = *(h4*)&e2d[((zb + 6) & 3) * 1024 + off];
                    h4 op = h4max3(eb, v0, v1);
                    h4 er = *(h4*)&ero[e0s * 1360 + (h + 1) * 40 + 4 + g * 4];
                    int vox = base + (zB * 160 + h0 + h) * 160 + w0 + g * 4;
                    h4 xv = *(const h4*)(src + vox);
                    h4 o;
                    o.a = __hmax2(__hsub2(xv.a, __hmax2(__hsub2(op.a, er.a), z2)), z2);
                    o.b = __hmax2(__hsub2(xv.b, __hmax2(__hsub2(op.b, er.b), z2)), z2);
                    *(h4*)(dst + vox) = o;
                    if (last) {
                        float2 f01 = __half22float2(o.a), f23 = __half22float2(o.b);
                        int q = vox >> 2;
                        unsigned nb4 = (g_Yb0[q >> 3] >> ((q & 7) * 4)) & 0xFu;
                        accS += f01.x + f01.y + f23.x + f23.y;
                        accSY += (nb4 & 1 ? f01.x : 0.f) + (nb4 & 2 ? f01.y : 0.f)
                               + (nb4 & 4 ? f23.x : 0.f) + (nb4 & 8 ? f23.y : 0.f);
                    }
                }
            }
        }
        // no trailing sync: every cross-step hazard has >=1 barrier in between
    }

    if (last) {
        float vals[2] = {accS, accSY};
        blockAddTo<2>(vals, g_acc + 10);
    }
}

// Bit-domain y skeleton, 4 output slices per block, 6-phase separable.
__device__ __forceinline__ void y_skel_block(unsigned int* su, int bi2, int it) {
    unsigned int* X  = su + YOFF_X;
    unsigned int* WT = su + YOFF_WT;
    unsigned int* WH = su + YOFF_WH;   // ring3
    unsigned int* E  = su + YOFF_E;    // ring2
    unsigned int* D  = su + YOFF_D;    // ring3

    int flip = it & 1;
    const unsigned int* src = flip ? g_Yb2 : g_Yb;
    unsigned int*       dst = flip ? g_Yb  : g_Yb2;
    bool last = (it == 7);

    int tid = threadIdx.x;
    int b = bi2 / 40, c = bi2 % 40;
    int z0 = c * 4, z1 = z0 + 3;
    int gbase = b * WBAT;

    float accY = 0.f, accYP = 0.f;

    for (int zl = z0 - 2; zl <= z1 + 2; ++zl) {
        // P1: load X slice zl (OOB = all ones)
        {
            bool zok = ((unsigned)zl < 160u);
            for (int i = tid; i < 800; i += 256)
                X[i] = zok ? src[gbase + zl * 800 + i] : 0xFFFFFFFFu;
        }
        __syncthreads();
        // P2: w-erode X -> WT
        for (int i = tid; i < 800; i += 256) {
            int j = i % W5;
            unsigned w = X[i];
            unsigned l = j > 0 ? X[i - 1] : 0xFFFFFFFFu;
            unsigned r = j < 4 ? X[i + 1] : 0xFFFFFFFFu;
            WT[i] = w & ((w << 1) | (l >> 31)) & ((w >> 1) | (r << 31));
        }
        __syncthreads();
        // P3: h-erode WT -> WH[zl]
        {
            int ws = (zl + 6) % 3;
            for (int i = tid; i < 800; i += 256) {
                int r = i / W5;
                unsigned w = WT[i];
                unsigned up = r > 0   ? WT[i - W5] : 0xFFFFFFFFu;
                unsigned dn = r < 159 ? WT[i + W5] : 0xFFFFFFFFu;
                WH[ws * 800 + i] = w & up & dn;
            }
        }
        __syncthreads();
        // P4: z-erode -> E[zl-1] (OOB slice -> 0)
        int ze = zl - 1;
        int es = (ze + 2) & 1;
        {
            bool zev = ((unsigned)ze < 160u);
            int wa = (ze + 5) % 3, wb = (ze + 6) % 3, wc = (ze + 7) % 3;
            for (int i = tid; i < 800; i += 256) {
                unsigned e = WH[wa * 800 + i] & WH[wb * 800 + i] & WH[wc * 800 + i];
                E[es * 800 + i] = zev ? e : 0u;
            }
        }
        __syncthreads();
        // P5: w-dilate E[zl-1] -> WT
        for (int i = tid; i < 800; i += 256) {
            int j = i % W5;
            unsigned w = E[es * 800 + i];
            unsigned l = j > 0 ? E[es * 800 + i - 1] : 0u;
            unsigned r = j < 4 ? E[es * 800 + i + 1] : 0u;
            WT[i] = w | (w << 1) | (l >> 31) | (w >> 1) | (r << 31);
        }
        __syncthreads();
        // P6: h-dilate WT -> D[zl-1]
        {
            int ds = (ze + 6) % 3;
            for (int i = tid; i < 800; i += 256) {
                int r = i / W5;
                unsigned w = WT[i];
                unsigned up = r > 0   ? WT[i - W5] : 0u;
                unsigned dn = r < 159 ? WT[i + W5] : 0u;
                D[ds * 800 + i] = w | up | dn;
            }
        }
        __syncthreads();
        // P7: combine at z = zl-2, x re-read from global
        int z = zl - 2;
        if (z >= z0) {
            int da = (z + 5) % 3, db = (z + 6) % 3, dc = (z + 7) % 3;
            int ez = (z + 2) & 1;
            for (int i = tid; i < 800; i += 256) {
                unsigned open = D[da * 800 + i] | D[db * 800 + i] | D[dc * 800 + i];
                unsigned x = src[gbase + z * 800 + i];
                int wi = gbase + z * 800 + i;
                unsigned dw = x & (~open | E[ez * 800 + i]);
                dst[wi] = dw;
                if (last && dw) {
                    accY += (float)__popc(dw);
#pragma unroll
                    for (int nb = 0; nb < 8; nb++) {
                        unsigned nb4 = (dw >> (nb * 4)) & 0xFu;
                        if (nb4) {
                            h4 p = ((const h4*)g_Porig)[wi * 8 + nb];
                            float2 pa = __half22float2(p.a), pb = __half22float2(p.b);
                            accYP += (nb4 & 1 ? pa.x : 0.f) + (nb4 & 2 ? pa.y : 0.f)
                                   + (nb4 & 4 ? pb.x : 0.f) + (nb4 & 8 ? pb.y : 0.f);
                        }
                    }
                }
            }
        }
    }

    if (last) {
        float vals[2] = {accY, accYP};
        blockAddTo<2>(vals, g_acc + 12);
    }
}

__global__ void __launch_bounds__(256, 4) k_skel(int it) {
    extern __shared__ __half smh[];
    int bi = blockIdx.x;
    if (bi < 500) p_skel_block(smh, bi, it);
    else          y_skel_block((unsigned int*)smh, bi - 500, it);
}

__global__ void k_fin(float* out) {
    double ce = g_acc[0] / (double)NTOT;
    double dsum = 0.0;
#pragma unroll
    for (int c = 0; c < 3; c++) {
        double I = g_acc[1 + c], P = g_acc[4 + c], T = g_acc[7 + c];
        dsum += (2.0 * I + 1e-5) / (P + T + 1e-5);
    }
    double base = ce + (1.0 - dsum / 3.0);
    double tprec = g_acc[11] / (g_acc[10] + 1e-6);
    double tsens = g_acc[13] / (g_acc[12] + 1e-6);
    double cl = 2.0 * tprec * tsens / (tprec + tsens + 1e-6);
    out[0] = (float)(base + 0.5 * (1.0 - cl));
}

extern "C" void kernel_launch(void* const* d_in, const int* in_sizes, int n_in,
                              void* d_out, int out_size) {
    const float* logits = (const float*)d_in[0];
    const int* target = (const int*)d_in[1];

    cudaFuncSetAttribute((const void*)k_skel,
                         cudaFuncAttributeMaxDynamicSharedMemorySize, SM_BYTES);

    k_zero<<<1, 32>>>();
    k_init<<<NQ / 1024, 256>>>(logits, target);
    for (int it = 0; it < 8; ++it)
        k_skel<<<580, 256, SM_BYTES>>>(it);
    k_fin<<<1, 1>>>((float*)d_out);
}

// round 16
// speedup vs baseline: 1.4357x; 1.0004x over previous
#include <cuda_runtime.h>
#include <cuda_fp16.h>

#define SVOL  4096000        // 160^3
#define NTOT  8192000        // 2 * 160^3
#define NQ    2048000        // NTOT / 4

// ---- p skeleton smem layout (halves), tile 32x32, zchunk 16, 2 z-slices per iter ----
#define OFF_STAGE 0          // 2 x [36][48]   (stride 1728)
#define OFF_ROWMN 3456       // 2 x [36][40]   (stride 1440)
#define OFF_M2D   6336       // ring4 [34][40] (stride 1360)
#define OFF_ERO   11776      // ring3 [34][40] (stride 1360)
#define OFF_RMAX  15856      // 2 x [34][32]   (stride 1088)
#define OFF_E2D   18032      // ring4 [32][32] (stride 1024)
#define SM_HALVES 22128
#define SM_BYTES  (SM_HALVES * 2)   // 44256

// ---- y bit skeleton smem layout (words) — 6-phase separable ----
#define W5    5
#define WSL   800
#define WBAT  128000
#define YW    256000
#define YOFF_X   0           // [800]
#define YOFF_WT  800         // [800] transient (w-erode / w-dilate)
#define YOFF_WH  1600        // ring3 [800]
#define YOFF_E   4000        // ring2 [800]
#define YOFF_D   5600        // ring3 [800]

#define HPINF __ushort_as_half((unsigned short)0x7C00)
#define HNINF __ushort_as_half((unsigned short)0xFC00)

struct __align__(8) h4 { __half2 a, b; };

__device__ double g_acc[14];         // zero-initialized at load; k_fin re-zeroes after use
__device__ __half g_Xp[NTOT];
__device__ __half g_Xp2[NTOT];
__device__ __half g_Porig[NTOT];
__device__ unsigned int g_Yb0[YW];
__device__ unsigned int g_Yb[YW];
__device__ unsigned int g_Yb2[YW];

__device__ __forceinline__ h4 h4fill(__half v) {
    h4 o; o.a = __half2half2(v); o.b = o.a; return o;
}
__device__ __forceinline__ h4 h4min3(h4 x, h4 y, h4 z) {
    h4 o;
    o.a = __hmin2(x.a, __hmin2(y.a, z.a));
    o.b = __hmin2(x.b, __hmin2(y.b, z.b));
    return o;
}
__device__ __forceinline__ h4 h4max3(h4 x, h4 y, h4 z) {
    h4 o;
    o.a = __hmax2(x.a, __hmax2(y.a, z.a));
    o.b = __hmax2(x.b, __hmax2(y.b, z.b));
    return o;
}
__device__ __forceinline__ h4 shiftMin(__half l, h4 c, __half r) {
    __half2 sl  = __halves2half2(l, __low2half(c.a));
    __half2 sr  = __halves2half2(__high2half(c.a), __low2half(c.b));
    __half2 sr2 = __halves2half2(__high2half(c.b), r);
    h4 o;
    o.a = __hmin2(__hmin2(sl, c.a), sr);
    o.b = __hmin2(__hmin2(sr, c.b), sr2);
    return o;
}
__device__ __forceinline__ h4 shiftMax(__half l, h4 c, __half r) {
    __half2 sl  = __halves2half2(l, __low2half(c.a));
    __half2 sr  = __halves2half2(__high2half(c.a), __low2half(c.b));
    __half2 sr2 = __halves2half2(__high2half(c.b), r);
    h4 o;
    o.a = __hmax2(__hmax2(sl, c.a), sr);
    o.b = __hmax2(__hmax2(sr, c.b), sr2);
    return o;
}

template <int NV>
__device__ __forceinline__ void blockAddTo(const float* vals, double* gout) {
    __shared__ float red[NV][8];
    int tid = threadIdx.x, lane = tid & 31, w = tid >> 5;
#pragma unroll
    for (int k = 0; k < NV; k++) {
        float v = vals[k];
#pragma unroll
        for (int o = 16; o; o >>= 1) v += __shfl_down_sync(0xffffffffu, v, o);
        if (lane == 0) red[k][w] = v;
    }
    __syncthreads();
    if (w == 0) {
#pragma unroll
        for (int k = 0; k < NV; k++) {
            float v = (lane < 8) ? red[k][lane] : 0.0f;
#pragma unroll
            for (int o = 4; o; o >>= 1) v += __shfl_down_sync(0xffffffffu, v, o);
            if (lane == 0) atomicAdd(&gout[k], (double)v);
        }
    }
}

// Fused: log-softmax, CE, dice accumulators, Porig (fp16), y bit-pack.
// 4 quads (16 voxels) per thread; 2000 blocks x 256.
__global__ void __launch_bounds__(256) k_init(const float* __restrict__ logits,
                                              const int* __restrict__ target) {
    __shared__ unsigned char nib[1024];
    int tid = threadIdx.x;
    int q0 = blockIdx.x * 1024 + tid;

    float ce = 0.f, i0 = 0.f, i1 = 0.f, i2 = 0.f;
    float s0 = 0.f, s1 = 0.f, s2 = 0.f, c0 = 0.f, c1 = 0.f, c2 = 0.f;

#pragma unroll
    for (int u = 0; u < 4; u++) {
        int q = q0 + u * 256;
        int e = q * 4;
        int b = (e >= SVOL) ? 1 : 0;
        int s = e - b * SVOL;
        const float* lp = logits + (size_t)b * 3 * SVOL + s;
        float4 L0 = *(const float4*)(lp);
        float4 L1 = *(const float4*)(lp + SVOL);
        float4 L2 = *(const float4*)(lp + 2 * SVOL);
        int4 ti = ((const int4*)target)[q];
        int tg[4] = {ti.x, ti.y, ti.z, ti.w};
        float a0[4] = {L0.x, L0.y, L0.z, L0.w};
        float a1[4] = {L1.x, L1.y, L1.z, L1.w};
        float a2[4] = {L2.x, L2.y, L2.z, L2.w};

        float pv[4];
        unsigned nb = 0;
#pragma unroll
        for (int j = 0; j < 4; j++) {
            float x0 = a0[j], x1 = a1[j], x2 = a2[j];
            float m = fmaxf(x0, fmaxf(x1, x2));
            float e0 = __expf(x0 - m), e1 = __expf(x1 - m), e2 = __expf(x2 - m);
            float sum = e0 + e1 + e2;
            float inv = __fdividef(1.0f, sum);
            float p0 = e0 * inv, p1 = e1 * inv, p2 = e2 * inv;
            float ls = __logf(sum);
            int t = tg[j];
            float lt = (t == 0) ? x0 : ((t == 1) ? x1 : x2);
            ce += (m + ls - lt);
            s0 += p0; s1 += p1; s2 += p2;
            if (t == 0)      { i0 += p0; c0 += 1.f; }
            else if (t == 1) { i1 += p1; c1 += 1.f; }
            else             { i2 += p2; c2 += 1.f; }
            pv[j] = fminf(fmaxf(1.0f - p0, 0.0f), 1.0f);
            if (t != 0) nb |= (1u << j);
        }
        h4 PV;
        PV.a = __floats2half2_rn(pv[0], pv[1]);
        PV.b = __floats2half2_rn(pv[2], pv[3]);
        ((h4*)g_Porig)[q] = PV;      // iteration 0 reads Porig directly
        nib[u * 256 + tid] = (unsigned char)nb;
    }
    __syncthreads();
    // nib[idx] holds quad blockIdx*1024 + idx, so word wi = blockIdx*128 + tid
    // packs quads wi*8 .. wi*8+7.
    if (tid < 128) {
        unsigned w = 0;
#pragma unroll
        for (int k = 0; k < 8; k++)
            w |= ((unsigned)nib[tid * 8 + k]) << (4 * k);
        int wi = blockIdx.x * 128 + tid;
        g_Yb0[wi] = w;
        g_Yb[wi] = w;
    }

    float vals[10] = {ce, i0, i1, i2, s0, s1, s2, c0, c1, c2};
    blockAddTo<10>(vals, g_acc);
}

// ---------------- merged skeleton iteration -----------------
// blocks [0,80): bit y skeleton (chunk 4, 6-phase separable) — fronted for scheduling.
// blocks [80,580): fp16 p skeleton (tile 32x32, zchunk 16, 2 slices/iter).
// On it==7, blocks also accumulate the clDice sums.

__device__ __forceinline__ void p_skel_block(__half* sm, int bi, int it) {
    __half* stage = sm + OFF_STAGE;
    __half* rowmn = sm + OFF_ROWMN;
    __half* m2d   = sm + OFF_M2D;
    __half* ero   = sm + OFF_ERO;
    __half* rmax  = sm + OFF_RMAX;
    __half* e2d   = sm + OFF_E2D;

    const __half* src = (it == 0) ? g_Porig : ((it & 1) ? g_Xp2 : g_Xp);
    __half*       dst = (it & 1) ? g_Xp : g_Xp2;
    bool last = (it == 7);

    int tid = threadIdx.x;
    int r = bi;
    int b = r / 250; r %= 250;
    int zc = r / 25; int t = r % 25;
    int h0 = (t / 5) * 32, w0 = (t % 5) * 32;
    int z0 = zc * 16;
    int base = b * SVOL;

    float accS = 0.f, accSY = 0.f;

    // one-time pad fill (both stage buffers, cols 0..5 and 42..47 stay +inf)
    for (int i = tid; i < 864; i += 256) {
        int s = i / 432, j = i % 432;
        int row = j / 12, c = j % 12;
        stage[s * 1728 + row * 48 + ((c < 6) ? c : c + 36)] = HPINF;
    }

    for (int zb = z0 - 2; zb <= z0 + 16; zb += 2) {
        // ---- A: stage x slices zb, zb+1 ----
        for (int i = tid; i < 576; i += 256) {
            int s = i / 288, j = i % 288;
            int row = j >> 3, qw = j & 7;
            int zl = zb + s;
            int h = h0 + row - 2;
            h4 v = h4fill(HPINF);
            if ((unsigned)zl < 160u && (unsigned)h < 160u)
                v = *(const h4*)(src + base + (zl * 160 + h) * 160 + w0 + qw * 4);
            *(h4*)&stage[s * 1728 + row * 48 + 8 + qw * 4] = v;
        }
        for (int i = tid; i < 288; i += 256) {            // halos w in {-2,-1,32,33}
            int s = i / 144, j = i % 144;
            int row = j >> 2, k = j & 3;
            int w = (k < 2) ? (k - 2) : (k + 30);
            int zl = zb + s;
            int h = h0 + row - 2, ww = w0 + w;
            __half v = HPINF;
            if ((unsigned)zl < 160u && (unsigned)h < 160u && (unsigned)ww < 160u)
                v = src[base + (zl * 160 + h) * 160 + ww];
            stage[s * 1728 + row * 48 + 8 + w] = v;
        }
        __syncthreads();
        // ---- B: row-min along w (both slices) ----
        for (int i = tid; i < 720; i += 256) {
            int s = i / 360, j = i % 360;
            int g = j % 10, row = j / 10;
            const __half* sp = &stage[s * 1728 + row * 48 + 4 + g * 4];
            h4 o = shiftMin(sp[-1], *(const h4*)sp, sp[4]);
            *(h4*)&rowmn[s * 1440 + row * 40 + g * 4] = o;
        }
        __syncthreads();
        // ---- C: col-min -> m2d[zb], m2d[zb+1]; z-min -> ero[zb-1], ero[zb] ----
        int mA = (zb + 6) & 3, mB = (zb + 7) & 3;       // slots zb-2, zb-1
        int m0 = (zb + 8) & 3, m1 = (zb + 9) & 3;       // slots zb,   zb+1
        int e0s = (zb + 8) % 3, e1s = (zb + 9) % 3;     // ero slots zb-1, zb
        bool zv0 = ((unsigned)(zb - 1) < 160u);
        bool zv1 = ((unsigned)zb < 160u);
        for (int i = tid; i < 340; i += 256) {
            int g = i % 10, mrow = i / 10;
            int off = mrow * 40 + g * 4;
            h4 v0, v1;
            {
                h4 r0 = *(h4*)&rowmn[off];
                h4 r1 = *(h4*)&rowmn[off + 40];
                h4 r2 = *(h4*)&rowmn[off + 80];
                v0 = h4min3(r0, r1, r2);
            }
            {
                h4 r0 = *(h4*)&rowmn[1440 + off];
                h4 r1 = *(h4*)&rowmn[1440 + off + 40];
                h4 r2 = *(h4*)&rowmn[1440 + off + 80];
                v1 = h4min3(r0, r1, r2);
            }
            *(h4*)&m2d[m0 * 1360 + off] = v0;
            *(h4*)&m2d[m1 * 1360 + off] = v1;
            h4 ma = *(h4*)&m2d[mA * 1360 + off];
            h4 mb = *(h4*)&m2d[mB * 1360 + off];
            h4 eA = zv0 ? h4min3(ma, mb, v0) : h4fill(HNINF);
            h4 eB = zv1 ? h4min3(mb, v0, v1) : h4fill(HNINF);
            *(h4*)&ero[e0s * 1360 + off] = eA;
            *(h4*)&ero[e1s * 1360 + off] = eB;
        }
        __syncthreads();
        // ---- D: row-max of ero[zb-1], ero[zb] ----
        for (int i = tid; i < 544; i += 256) {
            int s = i / 272, j = i % 272;
            int g = j & 7, row = j >> 3;
            int es = s ? e1s : e0s;
            const __half* ep = &ero[es * 1360 + row * 40 + 4 + g * 4];
            h4 o = shiftMax(ep[-1], *(const h4*)ep, ep[4]);
            *(h4*)&rmax[s * 1088 + row * 32 + g * 4] = o;
        }
        __syncthreads();
        // ---- E+F fused: col-max -> e2d[zb-1], e2d[zb]; outputs z = zb-2, zb-1 ----
        {
            int g = tid & 7, h = tid >> 3;     // exactly 256 items
            int off = h * 32 + g * 4;
            h4 v0, v1;
            {
                h4 r0 = *(h4*)&rmax[off];
                h4 r1 = *(h4*)&rmax[off + 32];
                h4 r2 = *(h4*)&rmax[off + 64];
                v0 = h4max3(r0, r1, r2);       // e2d[zb-1]
            }
            {
                h4 r0 = *(h4*)&rmax[1088 + off];
                h4 r1 = *(h4*)&rmax[1088 + off + 32];
                h4 r2 = *(h4*)&rmax[1088 + off + 64];
                v1 = h4max3(r0, r1, r2);       // e2d[zb]
            }
            *(h4*)&e2d[((zb + 7) & 3) * 1024 + off] = v0;
            *(h4*)&e2d[((zb + 8) & 3) * 1024 + off] = v1;

            int za = zb - 2;
            if (za >= z0) {
                __half2 z2 = __float2half2_rn(0.0f);
                // output za = zb-2: e2d slices za-1, za, za+1=v0
                {
                    h4 ea = *(h4*)&e2d[((zb + 5) & 3) * 1024 + off];   // e2d[zb-3]
                    h4 eb = *(h4*)&e2d[((zb + 6) & 3) * 1024 + off];   // e2d[zb-2]
                    h4 op = h4max3(ea, eb, v0);
                    h4 er = *(h4*)&ero[((zb + 7) % 3) * 1360 + (h + 1) * 40 + 4 + g * 4];
                    int vox = base + (za * 160 + h0 + h) * 160 + w0 + g * 4;
                    h4 xv = *(const h4*)(src + vox);
                    h4 o;
                    o.a = __hmax2(__hsub2(xv.a, __hmax2(__hsub2(op.a, er.a), z2)), z2);
                    o.b = __hmax2(__hsub2(xv.b, __hmax2(__hsub2(op.b, er.b), z2)), z2);
                    *(h4*)(dst + vox) = o;
                    if (last) {
                        float2 f01 = __half22float2(o.a), f23 = __half22float2(o.b);
                        int q = vox >> 2;
                        unsigned nb4 = (g_Yb0[q >> 3] >> ((q & 7) * 4)) & 0xFu;
                        accS += f01.x + f01.y + f23.x + f23.y;
                        accSY += (nb4 & 1 ? f01.x : 0.f) + (nb4 & 2 ? f01.y : 0.f)
                               + (nb4 & 4 ? f23.x : 0.f) + (nb4 & 8 ? f23.y : 0.f);
                    }
                }
                // output zB = zb-1: e2d slices zb-2, zb-1=v0, zb=v1
                {
                    int zB = zb - 1;
                    h4 eb = *(h4*)&e2d[((zb + 6) & 3) * 1024 + off];
                    h4 op = h4max3(eb, v0, v1);
                    h4 er = *(h4*)&ero[e0s * 1360 + (h + 1) * 40 + 4 + g * 4];
                    int vox = base + (zB * 160 + h0 + h) * 160 + w0 + g * 4;
                    h4 xv = *(const h4*)(src + vox);
                    h4 o;
                    o.a = __hmax2(__hsub2(xv.a, __hmax2(__hsub2(op.a, er.a), z2)), z2);
                    o.b = __hmax2(__hsub2(xv.b, __hmax2(__hsub2(op.b, er.b), z2)), z2);
                    *(h4*)(dst + vox) = o;
                    if (last) {
                        float2 f01 = __half22float2(o.a), f23 = __half22float2(o.b);
                        int q = vox >> 2;
                        unsigned nb4 = (g_Yb0[q >> 3] >> ((q & 7) * 4)) & 0xFu;
                        accS += f01.x + f01.y + f23.x + f23.y;
                        accSY += (nb4 & 1 ? f01.x : 0.f) + (nb4 & 2 ? f01.y : 0.f)
                               + (nb4 & 4 ? f23.x : 0.f) + (nb4 & 8 ? f23.y : 0.f);
                    }
                }
            }
        }
        // no trailing sync: every cross-step hazard has >=1 barrier in between
    }

    if (last) {
        float vals[2] = {accS, accSY};
        blockAddTo<2>(vals, g_acc + 10);
    }
}

// Bit-domain y skeleton, 4 output slices per block, 6-phase separable.
__device__ __forceinline__ void y_skel_block(unsigned int* su, int bi2, int it) {
    unsigned int* X  = su + YOFF_X;
    unsigned int* WT = su + YOFF_WT;
    unsigned int* WH = su + YOFF_WH;   // ring3
    unsigned int* E  = su + YOFF_E;    // ring2
    unsigned int* D  = su + YOFF_D;    // ring3

    int flip = it & 1;
    const unsigned int* src = flip ? g_Yb2 : g_Yb;
    unsigned int*       dst = flip ? g_Yb  : g_Yb2;
    bool last = (it == 7);

    int tid = threadIdx.x;
    int b = bi2 / 40, c = bi2 % 40;
    int z0 = c * 4, z1 = z0 + 3;
    int gbase = b * WBAT;

    float accY = 0.f, accYP = 0.f;

    for (int zl = z0 - 2; zl <= z1 + 2; ++zl) {
        // P1: load X slice zl (OOB = all ones)
        {
            bool zok = ((unsigned)zl < 160u);
            for (int i = tid; i < 800; i += 256)
                X[i] = zok ? src[gbase + zl * 800 + i] : 0xFFFFFFFFu;
        }
        __syncthreads();
        // P2: w-erode X -> WT
        for (int i = tid; i < 800; i += 256) {
            int j = i % W5;
            unsigned w = X[i];
            unsigned l = j > 0 ? X[i - 1] : 0xFFFFFFFFu;
            unsigned r = j < 4 ? X[i + 1] : 0xFFFFFFFFu;
            WT[i] = w & ((w << 1) | (l >> 31)) & ((w >> 1) | (r << 31));
        }
        __syncthreads();
        // P3: h-erode WT -> WH[zl]
        {
            int ws = (zl + 6) % 3;
            for (int i = tid; i < 800; i += 256) {
                int r = i / W5;
                unsigned w = WT[i];
                unsigned up = r > 0   ? WT[i - W5] : 0xFFFFFFFFu;
                unsigned dn = r < 159 ? WT[i + W5] : 0xFFFFFFFFu;
                WH[ws * 800 + i] = w & up & dn;
            }
        }
        __syncthreads();
        // P4: z-erode -> E[zl-1] (OOB slice -> 0)
        int ze = zl - 1;
        int es = (ze + 2) & 1;
        {
            bool zev = ((unsigned)ze < 160u);
            int wa = (ze + 5) % 3, wb = (ze + 6) % 3, wc = (ze + 7) % 3;
            for (int i = tid; i < 800; i += 256) {
                unsigned e = WH[wa * 800 + i] & WH[wb * 800 + i] & WH[wc * 800 + i];
                E[es * 800 + i] = zev ? e : 0u;
            }
        }
        __syncthreads();
        // P5: w-dilate E[zl-1] -> WT
        for (int i = tid; i < 800; i += 256) {
            int j = i % W5;
            unsigned w = E[es * 800 + i];
            unsigned l = j > 0 ? E[es * 800 + i - 1] : 0u;
            unsigned r = j < 4 ? E[es * 800 + i + 1] : 0u;
            WT[i] = w | (w << 1) | (l >> 31) | (w >> 1) | (r << 31);
        }
        __syncthreads();
        // P6: h-dilate WT -> D[zl-1]
        {
            int ds = (ze + 6) % 3;
            for (int i = tid; i < 800; i += 256) {
                int r = i / W5;
                unsigned w = WT[i];
                unsigned up = r > 0   ? WT[i - W5] : 0u;
                unsigned dn = r < 159 ? WT[i + W5] : 0u;
                D[ds * 800 + i] = w | up | dn;
            }
        }
        __syncthreads();
        // P7: combine at z = zl-2, x re-read from global
        int z = zl - 2;
        if (z >= z0) {
            int da = (z + 5) % 3, db = (z + 6) % 3, dc = (z + 7) % 3;
            int ez = (z + 2) & 1;
            for (int i = tid; i < 800; i += 256) {
                unsigned open = D[da * 800 + i] | D[db * 800 + i] | D[dc * 800 + i];
                unsigned x = src[gbase + z * 800 + i];
                int wi = gbase + z * 800 + i;
                unsigned dw = x & (~open | E[ez * 800 + i]);
                dst[wi] = dw;
                if (last && dw) {
                    accY += (float)__popc(dw);
#pragma unroll
                    for (int nb = 0; nb < 8; nb++) {
                        unsigned nb4 = (dw >> (nb * 4)) & 0xFu;
                        if (nb4) {
                            h4 p = ((const h4*)g_Porig)[wi * 8 + nb];
                            float2 pa = __half22float2(p.a), pb = __half22float2(p.b);
                            accYP += (nb4 & 1 ? pa.x : 0.f) + (nb4 & 2 ? pa.y : 0.f)
                                   + (nb4 & 4 ? pb.x : 0.f) + (nb4 & 8 ? pb.y : 0.f);
                        }
                    }
                }
            }
        }
    }

    if (last) {
        float vals[2] = {accY, accYP};
        blockAddTo<2>(vals, g_acc + 12);
    }
}

__global__ void __launch_bounds__(256, 4) k_skel(int it) {
    extern __shared__ __half smh[];
    int bi = blockIdx.x;
    if (bi < 80) y_skel_block((unsigned int*)smh, bi, it);
    else         p_skel_block(smh, bi - 80, it);
}

__global__ void k_fin(float* out) {
    double ce = g_acc[0] / (double)NTOT;
    double dsum = 0.0;
#pragma unroll
    for (int c = 0; c < 3; c++) {
        double I = g_acc[1 + c], P = g_acc[4 + c], T = g_acc[7 + c];
        dsum += (2.0 * I + 1e-5) / (P + T + 1e-5);
    }
    double base = ce + (1.0 - dsum / 3.0);
    double tprec = g_acc[11] / (g_acc[10] + 1e-6);
    double tsens = g_acc[13] / (g_acc[12] + 1e-6);
    double cl = 2.0 * tprec * tsens / (tprec + tsens + 1e-6);
    out[0] = (float)(base + 0.5 * (1.0 - cl));
    // re-zero accumulators for the next (graph-replayed) invocation
#pragma unroll
    for (int i = 0; i < 14; i++) g_acc[i] = 0.0;
}

extern "C" void kernel_launch(void* const* d_in, const int* in_sizes, int n_in,
                              void* d_out, int out_size) {
    const float* logits = (const float*)d_in[0];
    const int* target = (const int*)d_in[1];

    cudaFuncSetAttribute((const void*)k_skel,
                         cudaFuncAttributeMaxDynamicSharedMemorySize, SM_BYTES);

    k_init<<<NQ / 1024, 256>>>(logits, target);
    for (int it = 0; it < 8; ++it)
        k_skel<<<580, 256, SM_BYTES>>>(it);
    k_fin<<<1, 1>>>((float*)d_out);
}